// round 1
// baseline (speedup 1.0000x reference)
#include <cuda_runtime.h>
#include <math.h>

#define Ncnt 4096
#define Dd   1024
#define Mq   4096
#define Cc   16
#define NB   64
#define NSTEP (Dd/NB)   // 16
#define REGC 0.1f

// ---------------- scratch (device globals; no allocations) ----------------
__device__ int   g_cnt[Cc];
__device__ int   g_off[Cc];
__device__ int   g_idx[Ncnt];
__device__ float g_r[Cc];        // kap + Nj
__device__ float g_invden[Cc];   // 1/(nu_ + Nj + d + 2)
__device__ float g_mu[Cc*Dd];
__device__ float g_L[Dd*Dd];     // prior Cholesky-ish factor (lower)
__device__ float g_B[Dd*Dd];     // base = L L^T + kap m^T m (lower valid)
__device__ float g_Sig[(size_t)Cc*Dd*Dd];     // 64 MB: sigma -> chol factor in place
__device__ float g_Xqt[(size_t)Dd*Mq];        // 16 MB: Xq transposed [d][m]
__device__ float g_Dz[(size_t)Cc*Dd*Mq];      // 256 MB: diff -> L^{-1} diff in place
__device__ float g_dn2[(size_t)Mq*Cc];        // ||diff||^2

// ---------------- class gather (deterministic, no atomics) ----------------
__global__ void k_gather(const int* __restrict__ y) {
    int c = threadIdx.x;
    if (c >= Cc) return;
    int cnt = 0;
    for (int i = 0; i < Ncnt; i++) cnt += (y[i] == c);
    g_cnt[c] = cnt;
    __syncthreads();
    int off = 0;
    for (int cc = 0; cc < c; cc++) off += g_cnt[cc];
    g_off[c] = off;
    int p = off;
    for (int i = 0; i < Ncnt; i++) if (y[i] == c) g_idx[p++] = i;
}

__global__ void k_scalars(const float* __restrict__ kappa, const float* __restrict__ nu) {
    int c = threadIdx.x;
    if (c >= Cc) return;
    float kap = fabsf(kappa[0]) + 1e-6f;
    float nu_ = fmaxf(nu[0], (float)Dd - 1.0f + 1e-6f);
    float Nj  = (float)g_cnt[c];
    g_r[c]      = kap + Nj;
    g_invden[c] = 1.0f / (nu_ + Nj + (float)Dd + 2.0f);
}

// mu[c] = (kap*m + sum_c) / (kap + Nj)
__global__ void k_mu(const float* __restrict__ X, const float* __restrict__ m,
                     const float* __restrict__ kappa) {
    int c = blockIdx.x;
    int j = blockIdx.y * 256 + threadIdx.x;
    int cnt = g_cnt[c], off = g_off[c];
    float s = 0.f;
    for (int k = 0; k < cnt; k++) s += X[(size_t)g_idx[off + k] * Dd + j];
    float kap = fabsf(kappa[0]) + 1e-6f;
    g_mu[c * Dd + j] = (kap * m[j] + s) / (kap + (float)cnt);
}

// L = diag(|triu_diag|) + strict-lower(triu_lower)
__global__ void k_buildL(const float* __restrict__ tdiag, const float* __restrict__ tlow) {
    int t = blockIdx.x * 256 + threadIdx.x;
    int i = t / Dd, j = t % Dd;
    float v;
    if (i == j)      v = fabsf(tdiag[i]);
    else if (i > j)  v = tlow[t];
    else             v = 0.f;
    g_L[t] = v;
}

// ---------------- shared-tile NT microkernel helpers ----------------
// As[kk][i] <- G[(row0+i)*ld + k0+kk], 64 rows x 16 k  (k-contiguous source)
__device__ __forceinline__ void mm_loadNT(float* sm, const float* __restrict__ G,
                                          int row0, int k0, int ld, int tid) {
    int i = tid >> 2;
    int q = (tid & 3) * 4;
    float4 v = *reinterpret_cast<const float4*>(G + (size_t)(row0 + i) * ld + k0 + q);
    sm[(q + 0) * 64 + i] = v.x;
    sm[(q + 1) * 64 + i] = v.y;
    sm[(q + 2) * 64 + i] = v.z;
    sm[(q + 3) * 64 + i] = v.w;
}
// Bs[kk][j] <- G[(k0+kk)*ld + col0+j], 16 k x 64 cols  (col-contiguous source)
__device__ __forceinline__ void mm_loadT(float* sm, const float* __restrict__ G,
                                         int k0, int col0, int ld, int tid) {
    int kk = tid >> 4;
    int j  = (tid & 15) * 4;
    float4 v = *reinterpret_cast<const float4*>(G + (size_t)(k0 + kk) * ld + col0 + j);
    *reinterpret_cast<float4*>(sm + kk * 64 + j) = v;
}

#define MM_INNER(As, Bs, acc, ty, tx)                                     \
    _Pragma("unroll")                                                     \
    for (int kk = 0; kk < 16; kk++) {                                     \
        float4 a = *reinterpret_cast<float4*>((As) + kk * 64 + (ty) * 4); \
        float4 b = *reinterpret_cast<float4*>((Bs) + kk * 64 + (tx) * 4); \
        acc[0][0] += a.x * b.x; acc[0][1] += a.x * b.y;                   \
        acc[0][2] += a.x * b.z; acc[0][3] += a.x * b.w;                   \
        acc[1][0] += a.y * b.x; acc[1][1] += a.y * b.y;                   \
        acc[1][2] += a.y * b.z; acc[1][3] += a.y * b.w;                   \
        acc[2][0] += a.z * b.x; acc[2][1] += a.z * b.y;                   \
        acc[2][2] += a.z * b.z; acc[2][3] += a.z * b.w;                   \
        acc[3][0] += a.w * b.x; acc[3][1] += a.w * b.y;                   \
        acc[3][2] += a.w * b.z; acc[3][3] += a.w * b.w;                   \
    }

// base = L L^T + kap m^T m   (lower tiles only)
__global__ void k_base(const float* __restrict__ m, const float* __restrict__ kappa) {
    int bi = blockIdx.x, bj = blockIdx.y;
    if (bj > bi) return;
    int tid = threadIdx.x, tx = tid & 15, ty = tid >> 4;
    __shared__ float As[16 * 64], Bs[16 * 64];
    float acc[4][4] = {};
    int kchunks = (bj + 1) * 4;   // L[j][k]=0 for k>j
    for (int kt = 0; kt < kchunks; kt++) {
        mm_loadNT(As, g_L, bi * 64, kt * 16, Dd, tid);
        mm_loadNT(Bs, g_L, bj * 64, kt * 16, Dd, tid);
        __syncthreads();
        MM_INNER(As, Bs, acc, ty, tx);
        __syncthreads();
    }
    float kap = fabsf(kappa[0]) + 1e-6f;
    for (int r = 0; r < 4; r++) {
        int i = bi * 64 + ty * 4 + r;
        for (int q = 0; q < 4; q++) {
            int j = bj * 64 + tx * 4 + q;
            g_B[(size_t)i * Dd + j] = acc[r][q] + kap * m[i] * m[j];
        }
    }
}

// sigma[c] = (base + X_c^T X_c - r_c mu mu^T) * invden   (lower tiles only)
__global__ void k_sigma(const float* __restrict__ X) {
    int bi = blockIdx.x, bj = blockIdx.y, c = blockIdx.z;
    if (bj > bi) return;
    int tid = threadIdx.x, tx = tid & 15, ty = tid >> 4;
    int cnt = g_cnt[c], off = g_off[c];
    __shared__ float As[16 * 64], Bs[16 * 64];
    float acc[4][4] = {};
    int kk = tid >> 4;
    int jj = (tid & 15) * 4;
    for (int kt = 0; kt < cnt; kt += 16) {
        int krow = kt + kk;
        float4 va = make_float4(0.f, 0.f, 0.f, 0.f), vb = va;
        if (krow < cnt) {
            const float* row = X + (size_t)g_idx[off + krow] * Dd;
            va = *reinterpret_cast<const float4*>(row + bi * 64 + jj);
            vb = *reinterpret_cast<const float4*>(row + bj * 64 + jj);
        }
        *reinterpret_cast<float4*>(As + kk * 64 + jj) = va;
        *reinterpret_cast<float4*>(Bs + kk * 64 + jj) = vb;
        __syncthreads();
        MM_INNER(As, Bs, acc, ty, tx);
        __syncthreads();
    }
    float rc = g_r[c], inv = g_invden[c];
    float* Sg = g_Sig + (size_t)c * Dd * Dd;
    for (int r = 0; r < 4; r++) {
        int i = bi * 64 + ty * 4 + r;
        float mui = g_mu[c * Dd + i];
        for (int q = 0; q < 4; q++) {
            int j = bj * 64 + tx * 4 + q;
            float v = g_B[(size_t)i * Dd + j] + acc[r][q] - rc * mui * g_mu[c * Dd + j];
            Sg[(size_t)i * Dd + j] = v * inv;
        }
    }
}

// ---------------- batched blocked Cholesky (in place, lower) ----------------
__global__ void k_chol_diag(int s) {
    int c = blockIdx.x, t = threadIdx.x;
    float* A = g_Sig + (size_t)c * Dd * Dd;
    __shared__ float Ld[64][65];
    for (int idx = t; idx < 64 * 64; idx += 256) {
        int r = idx >> 6, k = idx & 63;
        Ld[r][k] = A[(size_t)(s * 64 + r) * Dd + s * 64 + k];
    }
    __syncthreads();
    for (int j = 0; j < 64; j++) {
        if (t == 0) Ld[j][j] = sqrtf(Ld[j][j]);
        __syncthreads();
        float dinv = 1.0f / Ld[j][j];
        if (t > j && t < 64) Ld[t][j] *= dinv;
        __syncthreads();
        int k = j + 1 + t;
        if (k < 64) {
            float lkj = Ld[k][j];
            for (int r = k; r < 64; r++) Ld[r][k] -= Ld[r][j] * lkj;
        }
        __syncthreads();
    }
    for (int idx = t; idx < 64 * 64; idx += 256) {
        int r = idx >> 6, k = idx & 63;
        if (k <= r) A[(size_t)(s * 64 + r) * Dd + s * 64 + k] = Ld[r][k];
    }
}

// panel rows below the diagonal block: row-solve vs L_ss^T
__global__ void k_chol_panel(int s) {
    int c = blockIdx.x, t = threadIdx.x;
    float* A = g_Sig + (size_t)c * Dd * Dd;
    __shared__ float Ld[64][64];
    __shared__ float zsh[64][128];
    for (int idx = t; idx < 64 * 64; idx += 128) {
        int r = idx >> 6, k = idx & 63;
        Ld[r][k] = A[(size_t)(s * 64 + r) * Dd + s * 64 + k];
    }
    __syncthreads();
    int g = 64 * (s + 1) + blockIdx.y * 128 + t;
    if (g < Dd) {
        float* row = A + (size_t)g * Dd + s * 64;
        for (int j = 0; j < 64; j++) {
            float acc = row[j];
            for (int k = 0; k < j; k++) acc -= Ld[j][k] * zsh[k][t];
            float v = acc / Ld[j][j];
            zsh[j][t] = v;
            row[j] = v;
        }
    }
}

// trailing SYRK update: A[i][j] -= P_i P_j^T   (lower tiles)
__global__ void k_chol_syrk(int s) {
    int r0 = 64 * (s + 1);
    int bi = blockIdx.x, bj = blockIdx.y, c = blockIdx.z;
    if (bj > bi) return;
    int tid = threadIdx.x, tx = tid & 15, ty = tid >> 4;
    float* A = g_Sig + (size_t)c * Dd * Dd;
    int i0 = r0 + bi * 64, j0 = r0 + bj * 64;
    __shared__ float As[16 * 64], Bs[16 * 64];
    float acc[4][4] = {};
    for (int kt = 0; kt < 4; kt++) {
        mm_loadNT(As, A, i0, s * 64 + kt * 16, Dd, tid);
        mm_loadNT(Bs, A, j0, s * 64 + kt * 16, Dd, tid);
        __syncthreads();
        MM_INNER(As, Bs, acc, ty, tx);
        __syncthreads();
    }
    for (int r = 0; r < 4; r++) {
        int i = i0 + ty * 4 + r;
        for (int q = 0; q < 4; q++) {
            int j = j0 + tx * 4 + q;
            A[(size_t)i * Dd + j] -= acc[r][q];
        }
    }
}

// ---------------- predict side ----------------
__global__ void k_transpose(const float* __restrict__ Xq) {
    __shared__ float tile[32][33];
    int dcol = blockIdx.x * 32 + threadIdx.x;
    int m0 = blockIdx.y * 32;
#pragma unroll
    for (int q = 0; q < 4; q++)
        tile[threadIdx.y + q * 8][threadIdx.x] = Xq[(size_t)(m0 + threadIdx.y + q * 8) * Dd + dcol];
    __syncthreads();
    int d0 = blockIdx.x * 32;
    int mcol = m0 + threadIdx.x;
#pragma unroll
    for (int q = 0; q < 4; q++)
        g_Xqt[(size_t)(d0 + threadIdx.y + q * 8) * Mq + mcol] = tile[threadIdx.x][threadIdx.y + q * 8];
}

__global__ void k_initD() {
    int dimi = blockIdx.x, c = blockIdx.y;
    float muv = g_mu[c * Dd + dimi];
    const float4* src = reinterpret_cast<const float4*>(g_Xqt + (size_t)dimi * Mq);
    float4* dst = reinterpret_cast<float4*>(g_Dz + ((size_t)c * Dd + dimi) * Mq);
    for (int i = threadIdx.x; i < Mq / 4; i += 256) {
        float4 v = src[i];
        v.x -= muv; v.y -= muv; v.z -= muv; v.w -= muv;
        dst[i] = v;
    }
}

// forward substitution on diag block s: columns of Dz, 1 thread per RHS column
__global__ void k_trsolve(int s) {
    int c = blockIdx.x, t = threadIdx.x;
    const float* A = g_Sig + (size_t)c * Dd * Dd;
    __shared__ float Ld[64][64];
    __shared__ float zsh[64][128];
    for (int idx = t; idx < 64 * 64; idx += 128) {
        int r = idx >> 6, k = idx & 63;
        Ld[r][k] = A[(size_t)(s * 64 + r) * Dd + s * 64 + k];
    }
    __syncthreads();
    int mcol = blockIdx.y * 128 + t;
    float* Dp = g_Dz + ((size_t)c * Dd + s * 64) * Mq + mcol;
    for (int r = 0; r < 64; r++) {
        float acc = Dp[(size_t)r * Mq];
        for (int k = 0; k < r; k++) acc -= Ld[r][k] * zsh[k][t];
        float v = acc / Ld[r][r];
        zsh[r][t] = v;
        Dp[(size_t)r * Mq] = v;
    }
}

// trailing update: D[g][m] -= L[g][s-block] @ Z[s-block][m]
__global__ void k_trsm_upd(int s) {
    int c = blockIdx.z;
    int i0 = 64 * (s + 1) + blockIdx.x * 64;
    int j0 = blockIdx.y * 64;
    int tid = threadIdx.x, tx = tid & 15, ty = tid >> 4;
    const float* A = g_Sig + (size_t)c * Dd * Dd;
    float* Dp = g_Dz + (size_t)c * Dd * Mq;
    __shared__ float As[16 * 64], Bs[16 * 64];
    float acc[4][4] = {};
    for (int kt = 0; kt < 4; kt++) {
        mm_loadNT(As, A, i0, s * 64 + kt * 16, Dd, tid);
        mm_loadT(Bs, Dp, s * 64 + kt * 16, j0, Mq, tid);
        __syncthreads();
        MM_INNER(As, Bs, acc, ty, tx);
        __syncthreads();
    }
    for (int r = 0; r < 4; r++) {
        float4* p = reinterpret_cast<float4*>(Dp + (size_t)(i0 + ty * 4 + r) * Mq + j0 + tx * 4);
        float4 v = *p;
        v.x -= acc[r][0]; v.y -= acc[r][1]; v.z -= acc[r][2]; v.w -= acc[r][3];
        *p = v;
    }
}

// dn2[m][c] = ||xq_m - mu_c||^2
__global__ void k_dn2() {
    int c = blockIdx.y;
    int mcol = blockIdx.x * 256 + threadIdx.x;
    __shared__ float mush[256];
    float acc = 0.f;
    for (int d0 = 0; d0 < Dd; d0 += 256) {
        __syncthreads();
        mush[threadIdx.x] = g_mu[c * Dd + d0 + threadIdx.x];
        __syncthreads();
        for (int k = 0; k < 256; k++) {
            float df = g_Xqt[(size_t)(d0 + k) * Mq + mcol] - mush[k];
            acc += df * df;
        }
    }
    g_dn2[(size_t)mcol * Cc + c] = acc;
}

// logits = -(0.9 * ||L^{-1} diff||^2 + 0.1 * ||diff||^2)
__global__ void k_logits(float* __restrict__ out) {
    int c = blockIdx.y;
    int mcol = blockIdx.x * 256 + threadIdx.x;
    const float* Z = g_Dz + (size_t)c * Dd * Mq + mcol;
    float zs = 0.f;
    for (int d = 0; d < Dd; d++) {
        float z = Z[(size_t)d * Mq];
        zs += z * z;
    }
    out[(size_t)mcol * Cc + c] = -((1.0f - REGC) * zs + REGC * g_dn2[(size_t)mcol * Cc + c]);
}

// ---------------- orchestration ----------------
extern "C" void kernel_launch(void* const* d_in, const int* in_sizes, int n_in,
                              void* d_out, int out_size) {
    const float* X     = (const float*)d_in[0];
    const int*   y     = (const int*)d_in[1];
    const float* Xq    = (const float*)d_in[2];
    const float* m     = (const float*)d_in[3];
    const float* kappa = (const float*)d_in[4];
    const float* nu    = (const float*)d_in[5];
    const float* tdiag = (const float*)d_in[6];
    const float* tlow  = (const float*)d_in[7];
    float* out = (float*)d_out;

    k_gather<<<1, Cc>>>(y);
    k_scalars<<<1, Cc>>>(kappa, nu);
    k_mu<<<dim3(Cc, Dd / 256), 256>>>(X, m, kappa);
    k_buildL<<<(Dd * Dd) / 256, 256>>>(tdiag, tlow);
    k_base<<<dim3(16, 16), 256>>>(m, kappa);
    k_sigma<<<dim3(16, 16, Cc), 256>>>(X);

    for (int s = 0; s < NSTEP; s++) {
        k_chol_diag<<<Cc, 256>>>(s);
        int rows = Dd - 64 * (s + 1);
        if (rows > 0) {
            k_chol_panel<<<dim3(Cc, (rows + 127) / 128), 128>>>(s);
            int nb = rows / 64;
            k_chol_syrk<<<dim3(nb, nb, Cc), 256>>>(s);
        }
    }

    k_transpose<<<dim3(Dd / 32, Mq / 32), dim3(32, 8)>>>(Xq);
    k_initD<<<dim3(Dd, Cc), 256>>>();

    for (int s = 0; s < NSTEP; s++) {
        k_trsolve<<<dim3(Cc, Mq / 128), 128>>>(s);
        int rows = Dd - 64 * (s + 1);
        if (rows > 0)
            k_trsm_upd<<<dim3(rows / 64, Mq / 64, Cc), 256>>>(s);
    }

    k_dn2<<<dim3(Mq / 256, Cc), 256>>>();
    k_logits<<<dim3(Mq / 256, Cc), 256>>>(out);
}

// round 3
// speedup vs baseline: 1.2771x; 1.2771x over previous
#include <cuda_runtime.h>
#include <cuda_bf16.h>
#include <math.h>
#include <stdint.h>

#define Ncnt 4096
#define Dd   1024
#define Mq   4096
#define Cc   16
#define NB   64
#define NSTEP (Dd/NB)   // 16
#define REGC 0.1f

// ---------------- scratch (device globals; no allocations) ----------------
__device__ int   g_cnt[Cc];
__device__ int   g_off[Cc];
__device__ int   g_idx[Ncnt];
__device__ float g_r[Cc];
__device__ float g_invden[Cc];
__device__ float g_mu[Cc*Dd];
__device__ float g_mun[Cc];
__device__ float g_L[Dd*Dd];
__device__ float g_B[Dd*Dd];
__device__ float g_Sig[(size_t)Cc*Dd*Dd];         // 64 MB: sigma -> chol factor L_c
__device__ float g_U[(size_t)Cc*Dd*Dd];           // 64 MB: U = L_c^{-1}
__device__ __nv_bfloat16 g_Uh[(size_t)Cc*Dd*Dd];  // 32 MB
__device__ __nv_bfloat16 g_Ul[(size_t)Cc*Dd*Dd];  // 32 MB
__device__ __nv_bfloat16 g_Xh[(size_t)Mq*Dd];     // 8 MB
__device__ __nv_bfloat16 g_Xl[(size_t)Mq*Dd];     // 8 MB
__device__ float g_v[Cc*Dd];                      // U_c mu_c
__device__ float g_dn2[(size_t)Mq*Cc];            // ||xq-mu||^2

// ---------------- helpers ----------------
__device__ __forceinline__ uint32_t smem_u32(const void* p) {
    uint32_t a;
    asm("{ .reg .u64 t; cvta.to.shared.u64 t, %1; cvt.u32.u64 %0, t; }" : "=r"(a) : "l"(p));
    return a;
}
__device__ __forceinline__ void cpa16(uint32_t dst, const void* src) {
    asm volatile("cp.async.cg.shared.global [%0], [%1], 16;" :: "r"(dst), "l"(src) : "memory");
}
__device__ __forceinline__ void cpa_commit() {
    asm volatile("cp.async.commit_group;" ::: "memory");
}
__device__ __forceinline__ void cpa_wait0() {
    asm volatile("cp.async.wait_group 0;" ::: "memory");
}
__device__ __forceinline__ void cpa_wait1() {
    asm volatile("cp.async.wait_group 1;" ::: "memory");
}
__device__ __forceinline__ void ldm_x4(uint32_t* r, uint32_t a) {
    asm volatile("ldmatrix.sync.aligned.m8n8.x4.shared.b16 {%0,%1,%2,%3}, [%4];"
        : "=r"(r[0]), "=r"(r[1]), "=r"(r[2]), "=r"(r[3]) : "r"(a));
}
__device__ __forceinline__ void mma_bf16(float* c, const uint32_t* a, uint32_t b0, uint32_t b1) {
    asm volatile("mma.sync.aligned.m16n8k16.row.col.f32.bf16.bf16.f32 "
        "{%0,%1,%2,%3}, {%4,%5,%6,%7}, {%8,%9}, {%0,%1,%2,%3};"
        : "+f"(c[0]), "+f"(c[1]), "+f"(c[2]), "+f"(c[3])
        : "r"(a[0]), "r"(a[1]), "r"(a[2]), "r"(a[3]), "r"(b0), "r"(b1));
}

// ---------------- class gather (deterministic, no atomics) ----------------
__global__ void k_gather(const int* __restrict__ y) {
    int c = threadIdx.x;
    if (c >= Cc) return;
    int cnt = 0;
    for (int i = 0; i < Ncnt; i++) cnt += (y[i] == c);
    g_cnt[c] = cnt;
    __syncthreads();
    int off = 0;
    for (int cc = 0; cc < c; cc++) off += g_cnt[cc];
    g_off[c] = off;
    int p = off;
    for (int i = 0; i < Ncnt; i++) if (y[i] == c) g_idx[p++] = i;
}

__global__ void k_scalars(const float* __restrict__ kappa, const float* __restrict__ nu) {
    int c = threadIdx.x;
    if (c >= Cc) return;
    float kap = fabsf(kappa[0]) + 1e-6f;
    float nu_ = fmaxf(nu[0], (float)Dd - 1.0f + 1e-6f);
    float Nj  = (float)g_cnt[c];
    g_r[c]      = kap + Nj;
    g_invden[c] = 1.0f / (nu_ + Nj + (float)Dd + 2.0f);
}

__global__ void k_mu(const float* __restrict__ X, const float* __restrict__ m,
                     const float* __restrict__ kappa) {
    int c = blockIdx.x;
    int j = blockIdx.y * 256 + threadIdx.x;
    int cnt = g_cnt[c], off = g_off[c];
    float s = 0.f;
    for (int k = 0; k < cnt; k++) s += X[(size_t)g_idx[off + k] * Dd + j];
    float kap = fabsf(kappa[0]) + 1e-6f;
    g_mu[c * Dd + j] = (kap * m[j] + s) / (kap + (float)cnt);
}

__global__ void k_mun() {
    int c = blockIdx.x, t = threadIdx.x;
    __shared__ float red[256];
    float a = 0.f;
    for (int d = t; d < Dd; d += 256) { float v = g_mu[c * Dd + d]; a += v * v; }
    red[t] = a; __syncthreads();
    for (int st = 128; st; st >>= 1) { if (t < st) red[t] += red[t + st]; __syncthreads(); }
    if (t == 0) g_mun[c] = red[0];
}

__global__ void k_buildL(const float* __restrict__ tdiag, const float* __restrict__ tlow) {
    int t = blockIdx.x * 256 + threadIdx.x;
    int i = t / Dd, j = t % Dd;
    float v;
    if (i == j)      v = fabsf(tdiag[i]);
    else if (i > j)  v = tlow[t];
    else             v = 0.f;
    g_L[t] = v;
}

// ---------------- SIMT GEMM helpers ----------------
__device__ __forceinline__ void mm_loadNT(float* sm, const float* __restrict__ G,
                                          int row0, int k0, int ld, int tid) {
    int i = tid >> 2;
    int q = (tid & 3) * 4;
    float4 v = *reinterpret_cast<const float4*>(G + (size_t)(row0 + i) * ld + k0 + q);
    sm[(q + 0) * 64 + i] = v.x;
    sm[(q + 1) * 64 + i] = v.y;
    sm[(q + 2) * 64 + i] = v.z;
    sm[(q + 3) * 64 + i] = v.w;
}
__device__ __forceinline__ void mm_loadT(float* sm, const float* __restrict__ G,
                                         int k0, int col0, int ld, int tid) {
    int kk = tid >> 4;
    int j  = (tid & 15) * 4;
    float4 v = *reinterpret_cast<const float4*>(G + (size_t)(k0 + kk) * ld + col0 + j);
    *reinterpret_cast<float4*>(sm + kk * 64 + j) = v;
}

#define MM_INNER(As, Bs, acc, ty, tx)                                     \
    _Pragma("unroll")                                                     \
    for (int kk = 0; kk < 16; kk++) {                                     \
        float4 a = *reinterpret_cast<float4*>((As) + kk * 64 + (ty) * 4); \
        float4 b = *reinterpret_cast<float4*>((Bs) + kk * 64 + (tx) * 4); \
        acc[0][0] += a.x * b.x; acc[0][1] += a.x * b.y;                   \
        acc[0][2] += a.x * b.z; acc[0][3] += a.x * b.w;                   \
        acc[1][0] += a.y * b.x; acc[1][1] += a.y * b.y;                   \
        acc[1][2] += a.y * b.z; acc[1][3] += a.y * b.w;                   \
        acc[2][0] += a.z * b.x; acc[2][1] += a.z * b.y;                   \
        acc[2][2] += a.z * b.z; acc[2][3] += a.z * b.w;                   \
        acc[3][0] += a.w * b.x; acc[3][1] += a.w * b.y;                   \
        acc[3][2] += a.w * b.z; acc[3][3] += a.w * b.w;                   \
    }

__global__ void k_base(const float* __restrict__ m, const float* __restrict__ kappa) {
    int bi = blockIdx.x, bj = blockIdx.y;
    if (bj > bi) return;
    int tid = threadIdx.x, tx = tid & 15, ty = tid >> 4;
    __shared__ float As[16 * 64], Bs[16 * 64];
    float acc[4][4] = {};
    int kchunks = (bj + 1) * 4;
    for (int kt = 0; kt < kchunks; kt++) {
        mm_loadNT(As, g_L, bi * 64, kt * 16, Dd, tid);
        mm_loadNT(Bs, g_L, bj * 64, kt * 16, Dd, tid);
        __syncthreads();
        MM_INNER(As, Bs, acc, ty, tx);
        __syncthreads();
    }
    float kap = fabsf(kappa[0]) + 1e-6f;
    for (int r = 0; r < 4; r++) {
        int i = bi * 64 + ty * 4 + r;
        for (int q = 0; q < 4; q++) {
            int j = bj * 64 + tx * 4 + q;
            g_B[(size_t)i * Dd + j] = acc[r][q] + kap * m[i] * m[j];
        }
    }
}

__global__ void k_sigma(const float* __restrict__ X) {
    int bi = blockIdx.x, bj = blockIdx.y, c = blockIdx.z;
    if (bj > bi) return;
    int tid = threadIdx.x, tx = tid & 15, ty = tid >> 4;
    int cnt = g_cnt[c], off = g_off[c];
    __shared__ float As[16 * 64], Bs[16 * 64];
    float acc[4][4] = {};
    int kk = tid >> 4;
    int jj = (tid & 15) * 4;
    for (int kt = 0; kt < cnt; kt += 16) {
        int krow = kt + kk;
        float4 va = make_float4(0.f, 0.f, 0.f, 0.f), vb = va;
        if (krow < cnt) {
            const float* row = X + (size_t)g_idx[off + krow] * Dd;
            va = *reinterpret_cast<const float4*>(row + bi * 64 + jj);
            vb = *reinterpret_cast<const float4*>(row + bj * 64 + jj);
        }
        *reinterpret_cast<float4*>(As + kk * 64 + jj) = va;
        *reinterpret_cast<float4*>(Bs + kk * 64 + jj) = vb;
        __syncthreads();
        MM_INNER(As, Bs, acc, ty, tx);
        __syncthreads();
    }
    float rc = g_r[c], inv = g_invden[c];
    float* Sg = g_Sig + (size_t)c * Dd * Dd;
    for (int r = 0; r < 4; r++) {
        int i = bi * 64 + ty * 4 + r;
        float mui = g_mu[c * Dd + i];
        for (int q = 0; q < 4; q++) {
            int j = bj * 64 + tx * 4 + q;
            float v = g_B[(size_t)i * Dd + j] + acc[r][q] - rc * mui * g_mu[c * Dd + j];
            Sg[(size_t)i * Dd + j] = v * inv;
        }
    }
}

// ---------------- batched blocked Cholesky ----------------
__global__ void k_chol_diag(int s) {
    int c = blockIdx.x, t = threadIdx.x;
    float* A = g_Sig + (size_t)c * Dd * Dd;
    __shared__ float Ld[64][65];
    for (int idx = t; idx < 64 * 64; idx += 256) {
        int r = idx >> 6, k = idx & 63;
        Ld[r][k] = A[(size_t)(s * 64 + r) * Dd + s * 64 + k];
    }
    __syncthreads();
    for (int j = 0; j < 64; j++) {
        if (t == 0) Ld[j][j] = sqrtf(Ld[j][j]);
        __syncthreads();
        float dinv = 1.0f / Ld[j][j];
        if (t > j && t < 64) Ld[t][j] *= dinv;
        __syncthreads();
        int k = j + 1 + t;
        if (k < 64) {
            float lkj = Ld[k][j];
            for (int r = k; r < 64; r++) Ld[r][k] -= Ld[r][j] * lkj;
        }
        __syncthreads();
    }
    for (int idx = t; idx < 64 * 64; idx += 256) {
        int r = idx >> 6, k = idx & 63;
        if (k <= r) A[(size_t)(s * 64 + r) * Dd + s * 64 + k] = Ld[r][k];
    }
}

__global__ void k_chol_panel(int s) {
    int c = blockIdx.x, t = threadIdx.x;
    float* A = g_Sig + (size_t)c * Dd * Dd;
    __shared__ float Ld[64][64];
    __shared__ float zsh[64][128];
    for (int idx = t; idx < 64 * 64; idx += 128) {
        int r = idx >> 6, k = idx & 63;
        Ld[r][k] = A[(size_t)(s * 64 + r) * Dd + s * 64 + k];
    }
    __syncthreads();
    int g = 64 * (s + 1) + blockIdx.y * 128 + t;
    if (g < Dd) {
        float* row = A + (size_t)g * Dd + s * 64;
        for (int j = 0; j < 64; j++) {
            float acc = row[j];
            for (int k = 0; k < j; k++) acc -= Ld[j][k] * zsh[k][t];
            float v = acc / Ld[j][j];
            zsh[j][t] = v;
            row[j] = v;
        }
    }
}

__global__ void k_chol_syrk(int s) {
    int r0 = 64 * (s + 1);
    int bi = blockIdx.x, bj = blockIdx.y, c = blockIdx.z;
    if (bj > bi) return;
    int tid = threadIdx.x, tx = tid & 15, ty = tid >> 4;
    float* A = g_Sig + (size_t)c * Dd * Dd;
    int i0 = r0 + bi * 64, j0 = r0 + bj * 64;
    __shared__ float As[16 * 64], Bs[16 * 64];
    float acc[4][4] = {};
    for (int kt = 0; kt < 4; kt++) {
        mm_loadNT(As, A, i0, s * 64 + kt * 16, Dd, tid);
        mm_loadNT(Bs, A, j0, s * 64 + kt * 16, Dd, tid);
        __syncthreads();
        MM_INNER(As, Bs, acc, ty, tx);
        __syncthreads();
    }
    for (int r = 0; r < 4; r++) {
        int i = i0 + ty * 4 + r;
        for (int q = 0; q < 4; q++) {
            int j = j0 + tx * 4 + q;
            A[(size_t)i * Dd + j] -= acc[r][q];
        }
    }
}

// ---------------- TRTRI: U = L^{-1}, blocked solve on identity ----------------
__global__ void k_initI() {
    size_t t = (size_t)blockIdx.x * 256 + threadIdx.x;
    size_t ij = t & (size_t)(Dd * Dd - 1);
    int i = (int)(ij >> 10), j = (int)(ij & 1023);
    g_U[t] = (i == j) ? 1.0f : 0.0f;
}

__global__ void k_tri_solve(int s) {
    int c = blockIdx.x, t = threadIdx.x;
    const float* A = g_Sig + (size_t)c * Dd * Dd;
    __shared__ float Ld[64][64];
    __shared__ float zsh[64][128];
    for (int idx = t; idx < 64 * 64; idx += 128) {
        int r = idx >> 6, k = idx & 63;
        Ld[r][k] = A[(size_t)(s * 64 + r) * Dd + s * 64 + k];
    }
    __syncthreads();
    int jcol = blockIdx.y * 128 + t;
    float* Dp = g_U + ((size_t)c * Dd + s * 64) * Dd + jcol;
    for (int r = 0; r < 64; r++) {
        float acc = Dp[(size_t)r * Dd];
        for (int k = 0; k < r; k++) acc -= Ld[r][k] * zsh[k][t];
        float v = acc / Ld[r][r];
        zsh[r][t] = v;
        Dp[(size_t)r * Dd] = v;
    }
}

__global__ void k_tri_upd(int s) {
    int c = blockIdx.z;
    int i0 = 64 * (s + 1) + blockIdx.x * 64;
    int j0 = blockIdx.y * 64;
    int tid = threadIdx.x, tx = tid & 15, ty = tid >> 4;
    const float* A = g_Sig + (size_t)c * Dd * Dd;
    float* Dp = g_U + (size_t)c * Dd * Dd;
    __shared__ float As[16 * 64], Bs[16 * 64];
    float acc[4][4] = {};
    for (int kt = 0; kt < 4; kt++) {
        mm_loadNT(As, A, i0, s * 64 + kt * 16, Dd, tid);
        mm_loadT(Bs, Dp, s * 64 + kt * 16, j0, Dd, tid);
        __syncthreads();
        MM_INNER(As, Bs, acc, ty, tx);
        __syncthreads();
    }
    for (int r = 0; r < 4; r++) {
        float4* p = reinterpret_cast<float4*>(Dp + (size_t)(i0 + ty * 4 + r) * Dd + j0 + tx * 4);
        float4 v = *p;
        v.x -= acc[r][0]; v.y -= acc[r][1]; v.z -= acc[r][2]; v.w -= acc[r][3];
        *p = v;
    }
}

// ---------------- bf16 splits ----------------
__global__ void k_splitU() {
    size_t t = (size_t)blockIdx.x * 256 + threadIdx.x;
    float x = g_U[t];
    __nv_bfloat16 h = __float2bfloat16(x);
    g_Uh[t] = h;
    g_Ul[t] = __float2bfloat16(x - __bfloat162float(h));
}
__global__ void k_splitX(const float* __restrict__ Xq) {
    size_t t = (size_t)blockIdx.x * 256 + threadIdx.x;
    float x = Xq[t];
    __nv_bfloat16 h = __float2bfloat16(x);
    g_Xh[t] = h;
    g_Xl[t] = __float2bfloat16(x - __bfloat162float(h));
}

// v_c = U_c mu_c
__global__ void k_v() {
    int d = blockIdx.x, c = blockIdx.y, t = threadIdx.x;
    __shared__ float red[128];
    const float* Ur = g_U + ((size_t)c * Dd + d) * Dd;
    const float* mu = g_mu + c * Dd;
    float a = 0.f;
    for (int e = t; e < Dd; e += 128) a += Ur[e] * mu[e];
    red[t] = a; __syncthreads();
    for (int st = 64; st; st >>= 1) { if (t < st) red[t] += red[t + st]; __syncthreads(); }
    if (t == 0) g_v[c * Dd + d] = red[0];
}

// dn2[m][c] = ||xq||^2 - 2 xq.mu_c + ||mu_c||^2
__global__ void k_dn(const float* __restrict__ Xq) {
    int m = blockIdx.x, t = threadIdx.x;
    __shared__ float red[17][129];
    float dc[16];
#pragma unroll
    for (int c = 0; c < 16; c++) dc[c] = 0.f;
    float s2 = 0.f;
    for (int i = 0; i < 8; i++) {
        int d = t + i * 128;
        float x = Xq[(size_t)m * Dd + d];
        s2 += x * x;
#pragma unroll
        for (int c = 0; c < 16; c++) dc[c] += x * g_mu[c * Dd + d];
    }
#pragma unroll
    for (int c = 0; c < 16; c++) red[c][t] = dc[c];
    red[16][t] = s2;
    __syncthreads();
    for (int st = 64; st; st >>= 1) {
        if (t < st) {
#pragma unroll
            for (int r = 0; r < 17; r++) red[r][t] += red[r][t + st];
        }
        __syncthreads();
    }
    if (t < 16)
        g_dn2[(size_t)m * Cc + t] = red[16][0] - 2.f * red[t][0] + g_mun[t];
}

// ---------------- fused mma.sync kernel: q = ||U_c Xq^T - v_c||^2 -> logits ----
// grid (Mq/128, Cc), 256 threads (8 warps, 4x2), dyn smem 128 KB
// smem per stage (64 KB): Uh[128][64] Ul Xh Xl, 16 KB each, 16B-chunk XOR swizzle
#define STAGE_BYTES 65536
#define TILE_BYTES  16384
#define SM_FUSED_TOTAL (2*STAGE_BYTES)

extern "C" __global__ void __launch_bounds__(256, 1)
k_fused(float* __restrict__ out) {
    extern __shared__ char sm[];
    uint32_t smb = smem_u32(sm);
    int tid = threadIdx.x;
    int wid = tid >> 5, lid = tid & 31;
    int wr = wid >> 1, wc = wid & 1;       // 4x2 warps
    int sub = lid >> 3, r8 = lid & 7;
    int m0 = blockIdx.x * 128;
    int c = blockIdx.y;

    const __nv_bfloat16* Ah = g_Uh + ((size_t)c << 20);
    const __nv_bfloat16* Al = g_Ul + ((size_t)c << 20);

    float acc[2][8][4];
#pragma unroll
    for (int a = 0; a < 2; a++)
#pragma unroll
        for (int b = 0; b < 8; b++)
#pragma unroll
            for (int d = 0; d < 4; d++) acc[a][b][d] = 0.f;
    float qpart[16];
#pragma unroll
    for (int i = 0; i < 16; i++) qpart[i] = 0.f;

    // precompute per-lane ldmatrix row geometry
    int arow_base0 = wr * 32 + (sub & 1) * 8 + r8;       // + mf*16
    int acko = sub >> 1;
    int brow_base = (sub >> 1) * 8 + r8;                 // + nf2*16
    int bcko = sub & 1;

    for (int dt = 0; dt < 8; dt++) {
        int nb = (dt + 1) * 2;   // K chunks of 64
        // prefetch kb=0
        {
            uint32_t sb = smb;
            for (int idx = tid; idx < 1024; idx += 256) {
                int row = idx >> 3, ch = idx & 7;
                uint32_t dsw = row * 128 + ((ch ^ (row & 7)) << 4);
                size_t gu = (size_t)(dt * 128 + row) * Dd + ch * 8;
                size_t gx = (size_t)(m0 + row) * Dd + ch * 8;
                cpa16(sb + dsw, Ah + gu);
                cpa16(sb + TILE_BYTES + dsw, Al + gu);
                cpa16(sb + 2 * TILE_BYTES + dsw, g_Xh + gx);
                cpa16(sb + 3 * TILE_BYTES + dsw, g_Xl + gx);
            }
            cpa_commit();
        }
        for (int kb = 0; kb < nb; kb++) {
            int st = kb & 1;
            if (kb + 1 < nb) {
                uint32_t sb = smb + (st ^ 1) * STAGE_BYTES;
                int k0 = (kb + 1) * 64;
                for (int idx = tid; idx < 1024; idx += 256) {
                    int row = idx >> 3, ch = idx & 7;
                    uint32_t dsw = row * 128 + ((ch ^ (row & 7)) << 4);
                    size_t gu = (size_t)(dt * 128 + row) * Dd + k0 + ch * 8;
                    size_t gx = (size_t)(m0 + row) * Dd + k0 + ch * 8;
                    cpa16(sb + dsw, Ah + gu);
                    cpa16(sb + TILE_BYTES + dsw, Al + gu);
                    cpa16(sb + 2 * TILE_BYTES + dsw, g_Xh + gx);
                    cpa16(sb + 3 * TILE_BYTES + dsw, g_Xl + gx);
                }
                cpa_commit();
                cpa_wait1();
            } else {
                cpa_wait0();
            }
            __syncthreads();

            uint32_t uhb = smb + st * STAGE_BYTES;
            uint32_t ulb = uhb + TILE_BYTES;
            uint32_t xhb = uhb + 2 * TILE_BYTES;
            uint32_t xlb = uhb + 3 * TILE_BYTES;
#pragma unroll
            for (int ks = 0; ks < 4; ks++) {
                int k2 = ks * 2;
                uint32_t ah[2][4], al2[2][4], bh[4][4], bl[4][4];
#pragma unroll
                for (int mf = 0; mf < 2; mf++) {
                    int row = arow_base0 + mf * 16;
                    uint32_t off = row * 128 + (((k2 + acko) ^ (row & 7)) << 4);
                    ldm_x4(ah[mf], uhb + off);
                    ldm_x4(al2[mf], ulb + off);
                }
#pragma unroll
                for (int nf2 = 0; nf2 < 4; nf2++) {
                    int row = brow_base + (wc * 64 + nf2 * 16);
                    uint32_t off = row * 128 + (((k2 + bcko) ^ (row & 7)) << 4);
                    ldm_x4(bh[nf2], xhb + off);
                    ldm_x4(bl[nf2], xlb + off);
                }
#pragma unroll
                for (int mf = 0; mf < 2; mf++) {
#pragma unroll
                    for (int nf = 0; nf < 8; nf++) {
                        uint32_t b0h = bh[nf >> 1][(nf & 1) * 2];
                        uint32_t b1h = bh[nf >> 1][(nf & 1) * 2 + 1];
                        uint32_t b0l = bl[nf >> 1][(nf & 1) * 2];
                        uint32_t b1l = bl[nf >> 1][(nf & 1) * 2 + 1];
                        mma_bf16(acc[mf][nf], ah[mf], b0h, b1h);
                        mma_bf16(acc[mf][nf], ah[mf], b0l, b1l);
                        mma_bf16(acc[mf][nf], al2[mf], b0h, b1h);
                    }
                }
            }
            __syncthreads();
        }
        // epilogue for this d-row-block: subtract v, square, fold into qpart
#pragma unroll
        for (int mf = 0; mf < 2; mf++) {
            int dg = dt * 128 + wr * 32 + mf * 16 + (lid >> 2);
            float v0 = g_v[c * Dd + dg];
            float v1 = g_v[c * Dd + dg + 8];
#pragma unroll
            for (int nf = 0; nf < 8; nf++) {
                float z;
                z = acc[mf][nf][0] - v0; qpart[nf * 2 + 0] += z * z;
                z = acc[mf][nf][1] - v0; qpart[nf * 2 + 1] += z * z;
                z = acc[mf][nf][2] - v1; qpart[nf * 2 + 0] += z * z;
                z = acc[mf][nf][3] - v1; qpart[nf * 2 + 1] += z * z;
                acc[mf][nf][0] = 0.f; acc[mf][nf][1] = 0.f;
                acc[mf][nf][2] = 0.f; acc[mf][nf][3] = 0.f;
            }
        }
    }

    // deterministic cross-thread reduction: red[col][contrib]
    __syncthreads();
    float* red = reinterpret_cast<float*>(sm);   // 128*33 floats = 16.9 KB
#pragma unroll
    for (int nf = 0; nf < 8; nf++) {
#pragma unroll
        for (int b = 0; b < 2; b++) {
            int col = wc * 64 + nf * 8 + (lid & 3) * 2 + b;
            red[col * 33 + wr * 8 + (lid >> 2)] = qpart[nf * 2 + b];
        }
    }
    __syncthreads();
    if (tid < 128) {
        float q = 0.f;
#pragma unroll
        for (int i = 0; i < 32; i++) q += red[tid * 33 + i];
        int m = m0 + tid;
        out[(size_t)m * Cc + c] = -((1.0f - REGC) * q + REGC * g_dn2[(size_t)m * Cc + c]);
    }
}

// ---------------- orchestration ----------------
extern "C" void kernel_launch(void* const* d_in, const int* in_sizes, int n_in,
                              void* d_out, int out_size) {
    const float* X     = (const float*)d_in[0];
    const int*   y     = (const int*)d_in[1];
    const float* Xq    = (const float*)d_in[2];
    const float* m     = (const float*)d_in[3];
    const float* kappa = (const float*)d_in[4];
    const float* nu    = (const float*)d_in[5];
    const float* tdiag = (const float*)d_in[6];
    const float* tlow  = (const float*)d_in[7];
    float* out = (float*)d_out;

    cudaFuncSetAttribute((const void*)k_fused,
                         cudaFuncAttributeMaxDynamicSharedMemorySize, SM_FUSED_TOTAL);

    k_gather<<<1, Cc>>>(y);
    k_scalars<<<1, Cc>>>(kappa, nu);
    k_mu<<<dim3(Cc, Dd / 256), 256>>>(X, m, kappa);
    k_mun<<<Cc, 256>>>();
    k_buildL<<<(Dd * Dd) / 256, 256>>>(tdiag, tlow);
    k_base<<<dim3(16, 16), 256>>>(m, kappa);
    k_sigma<<<dim3(16, 16, Cc), 256>>>(X);

    for (int s = 0; s < NSTEP; s++) {
        k_chol_diag<<<Cc, 256>>>(s);
        int rows = Dd - 64 * (s + 1);
        if (rows > 0) {
            k_chol_panel<<<dim3(Cc, (rows + 127) / 128), 128>>>(s);
            int nb = rows / 64;
            k_chol_syrk<<<dim3(nb, nb, Cc), 256>>>(s);
        }
    }

    // TRTRI
    k_initI<<<(int)(((size_t)Cc * Dd * Dd) / 256), 256>>>();
    for (int s = 0; s < NSTEP; s++) {
        int ncol = ((s + 1) * 64 + 127) / 128;
        k_tri_solve<<<dim3(Cc, ncol), 128>>>(s);
        int rows = Dd - 64 * (s + 1);
        if (rows > 0)
            k_tri_upd<<<dim3(rows / 64, s + 1, Cc), 256>>>(s);
    }

    k_splitU<<<(int)(((size_t)Cc * Dd * Dd) / 256), 256>>>();
    k_splitX<<<(int)(((size_t)Mq * Dd) / 256), 256>>>(Xq);
    k_v<<<dim3(Dd, Cc), 128>>>();
    k_dn<<<Mq, 128>>>(Xq);

    k_fused<<<dim3(Mq / 128, Cc), 256, SM_FUSED_TOTAL>>>(out);
}

// round 4
// speedup vs baseline: 1.2795x; 1.0019x over previous
#include <cuda_runtime.h>
#include <cuda_bf16.h>
#include <math.h>
#include <stdint.h>

#define Ncnt 4096
#define Dd   1024
#define Mq   4096
#define Cc   16
#define NB   64
#define NSTEP (Dd/NB)   // 16
#define REGC 0.1f

// ---------------- scratch (device globals; no allocations) ----------------
__device__ int   g_cnt[Cc];
__device__ int   g_off[Cc];
__device__ int   g_idx[Ncnt];
__device__ float g_r[Cc];
__device__ float g_invden[Cc];
__device__ float g_mu[Cc*Dd];
__device__ float g_mun[Cc];
__device__ float g_L[Dd*Dd];
__device__ float g_B[Dd*Dd];
__device__ float g_Sig[(size_t)Cc*Dd*Dd];         // 64 MB: sigma -> chol factor L_c
__device__ float g_U[(size_t)Cc*Dd*Dd];           // 64 MB: U = L_c^{-1}
__device__ __nv_bfloat16 g_Uh[(size_t)Cc*Dd*Dd];  // 32 MB
__device__ __nv_bfloat16 g_Ul[(size_t)Cc*Dd*Dd];  // 32 MB
__device__ __nv_bfloat16 g_Xh[(size_t)Mq*Dd];     // 8 MB
__device__ __nv_bfloat16 g_Xl[(size_t)Mq*Dd];     // 8 MB
__device__ float g_v[Cc*Dd];                      // U_c mu_c
__device__ float g_dn2[(size_t)Mq*Cc];            // ||xq-mu||^2

// ---------------- helpers ----------------
__device__ __forceinline__ uint32_t smem_u32(const void* p) {
    uint32_t a;
    asm("{ .reg .u64 t; cvta.to.shared.u64 t, %1; cvt.u32.u64 %0, t; }" : "=r"(a) : "l"(p));
    return a;
}
__device__ __forceinline__ void cpa16(uint32_t dst, const void* src) {
    asm volatile("cp.async.cg.shared.global [%0], [%1], 16;" :: "r"(dst), "l"(src) : "memory");
}
__device__ __forceinline__ void cpa_commit() {
    asm volatile("cp.async.commit_group;" ::: "memory");
}
__device__ __forceinline__ void cpa_wait0() {
    asm volatile("cp.async.wait_group 0;" ::: "memory");
}
__device__ __forceinline__ void cpa_wait1() {
    asm volatile("cp.async.wait_group 1;" ::: "memory");
}
__device__ __forceinline__ void ldm_x4(uint32_t* r, uint32_t a) {
    asm volatile("ldmatrix.sync.aligned.m8n8.x4.shared.b16 {%0,%1,%2,%3}, [%4];"
        : "=r"(r[0]), "=r"(r[1]), "=r"(r[2]), "=r"(r[3]) : "r"(a));
}
__device__ __forceinline__ void mma_bf16(float* c, const uint32_t* a, uint32_t b0, uint32_t b1) {
    asm volatile("mma.sync.aligned.m16n8k16.row.col.f32.bf16.bf16.f32 "
        "{%0,%1,%2,%3}, {%4,%5,%6,%7}, {%8,%9}, {%0,%1,%2,%3};"
        : "+f"(c[0]), "+f"(c[1]), "+f"(c[2]), "+f"(c[3])
        : "r"(a[0]), "r"(a[1]), "r"(a[2]), "r"(a[3]), "r"(b0), "r"(b1));
}

// ---------------- class gather (deterministic, no atomics) ----------------
__global__ void k_gather(const int* __restrict__ y) {
    int c = threadIdx.x;
    if (c >= Cc) return;
    int cnt = 0;
    for (int i = 0; i < Ncnt; i++) cnt += (y[i] == c);
    g_cnt[c] = cnt;
    __syncthreads();
    int off = 0;
    for (int cc = 0; cc < c; cc++) off += g_cnt[cc];
    g_off[c] = off;
    int p = off;
    for (int i = 0; i < Ncnt; i++) if (y[i] == c) g_idx[p++] = i;
}

__global__ void k_scalars(const float* __restrict__ kappa, const float* __restrict__ nu) {
    int c = threadIdx.x;
    if (c >= Cc) return;
    float kap = fabsf(kappa[0]) + 1e-6f;
    float nu_ = fmaxf(nu[0], (float)Dd - 1.0f + 1e-6f);
    float Nj  = (float)g_cnt[c];
    g_r[c]      = kap + Nj;
    g_invden[c] = 1.0f / (nu_ + Nj + (float)Dd + 2.0f);
}

__global__ void k_mu(const float* __restrict__ X, const float* __restrict__ m,
                     const float* __restrict__ kappa) {
    int c = blockIdx.x;
    int j = blockIdx.y * 256 + threadIdx.x;
    int cnt = g_cnt[c], off = g_off[c];
    float s = 0.f;
    for (int k = 0; k < cnt; k++) s += X[(size_t)g_idx[off + k] * Dd + j];
    float kap = fabsf(kappa[0]) + 1e-6f;
    g_mu[c * Dd + j] = (kap * m[j] + s) / (kap + (float)cnt);
}

__global__ void k_mun() {
    int c = blockIdx.x, t = threadIdx.x;
    __shared__ float red[256];
    float a = 0.f;
    for (int d = t; d < Dd; d += 256) { float v = g_mu[c * Dd + d]; a += v * v; }
    red[t] = a; __syncthreads();
    for (int st = 128; st; st >>= 1) { if (t < st) red[t] += red[t + st]; __syncthreads(); }
    if (t == 0) g_mun[c] = red[0];
}

__global__ void k_buildL(const float* __restrict__ tdiag, const float* __restrict__ tlow) {
    int t = blockIdx.x * 256 + threadIdx.x;
    int i = t / Dd, j = t % Dd;
    float v;
    if (i == j)      v = fabsf(tdiag[i]);
    else if (i > j)  v = tlow[t];
    else             v = 0.f;
    g_L[t] = v;
}

// ---------------- SIMT GEMM helpers ----------------
__device__ __forceinline__ void mm_loadNT(float* sm, const float* __restrict__ G,
                                          int row0, int k0, int ld, int tid) {
    int i = tid >> 2;
    int q = (tid & 3) * 4;
    float4 v = *reinterpret_cast<const float4*>(G + (size_t)(row0 + i) * ld + k0 + q);
    sm[(q + 0) * 64 + i] = v.x;
    sm[(q + 1) * 64 + i] = v.y;
    sm[(q + 2) * 64 + i] = v.z;
    sm[(q + 3) * 64 + i] = v.w;
}
__device__ __forceinline__ void mm_loadT(float* sm, const float* __restrict__ G,
                                         int k0, int col0, int ld, int tid) {
    int kk = tid >> 4;
    int j  = (tid & 15) * 4;
    float4 v = *reinterpret_cast<const float4*>(G + (size_t)(k0 + kk) * ld + col0 + j);
    *reinterpret_cast<float4*>(sm + kk * 64 + j) = v;
}

#define MM_INNER(As, Bs, acc, ty, tx)                                     \
    _Pragma("unroll")                                                     \
    for (int kk = 0; kk < 16; kk++) {                                     \
        float4 a = *reinterpret_cast<float4*>((As) + kk * 64 + (ty) * 4); \
        float4 b = *reinterpret_cast<float4*>((Bs) + kk * 64 + (tx) * 4); \
        acc[0][0] += a.x * b.x; acc[0][1] += a.x * b.y;                   \
        acc[0][2] += a.x * b.z; acc[0][3] += a.x * b.w;                   \
        acc[1][0] += a.y * b.x; acc[1][1] += a.y * b.y;                   \
        acc[1][2] += a.y * b.z; acc[1][3] += a.y * b.w;                   \
        acc[2][0] += a.z * b.x; acc[2][1] += a.z * b.y;                   \
        acc[2][2] += a.z * b.z; acc[2][3] += a.z * b.w;                   \
        acc[3][0] += a.w * b.x; acc[3][1] += a.w * b.y;                   \
        acc[3][2] += a.w * b.z; acc[3][3] += a.w * b.w;                   \
    }

__global__ void k_base(const float* __restrict__ m, const float* __restrict__ kappa) {
    int bi = blockIdx.x, bj = blockIdx.y;
    if (bj > bi) return;
    int tid = threadIdx.x, tx = tid & 15, ty = tid >> 4;
    __shared__ float As[16 * 64], Bs[16 * 64];
    float acc[4][4] = {};
    int kchunks = (bj + 1) * 4;
    for (int kt = 0; kt < kchunks; kt++) {
        mm_loadNT(As, g_L, bi * 64, kt * 16, Dd, tid);
        mm_loadNT(Bs, g_L, bj * 64, kt * 16, Dd, tid);
        __syncthreads();
        MM_INNER(As, Bs, acc, ty, tx);
        __syncthreads();
    }
    float kap = fabsf(kappa[0]) + 1e-6f;
    for (int r = 0; r < 4; r++) {
        int i = bi * 64 + ty * 4 + r;
        for (int q = 0; q < 4; q++) {
            int j = bj * 64 + tx * 4 + q;
            g_B[(size_t)i * Dd + j] = acc[r][q] + kap * m[i] * m[j];
        }
    }
}

__global__ void k_sigma(const float* __restrict__ X) {
    int bi = blockIdx.x, bj = blockIdx.y, c = blockIdx.z;
    if (bj > bi) return;
    int tid = threadIdx.x, tx = tid & 15, ty = tid >> 4;
    int cnt = g_cnt[c], off = g_off[c];
    __shared__ float As[16 * 64], Bs[16 * 64];
    float acc[4][4] = {};
    int kk = tid >> 4;
    int jj = (tid & 15) * 4;
    for (int kt = 0; kt < cnt; kt += 16) {
        int krow = kt + kk;
        float4 va = make_float4(0.f, 0.f, 0.f, 0.f), vb = va;
        if (krow < cnt) {
            const float* row = X + (size_t)g_idx[off + krow] * Dd;
            va = *reinterpret_cast<const float4*>(row + bi * 64 + jj);
            vb = *reinterpret_cast<const float4*>(row + bj * 64 + jj);
        }
        *reinterpret_cast<float4*>(As + kk * 64 + jj) = va;
        *reinterpret_cast<float4*>(Bs + kk * 64 + jj) = vb;
        __syncthreads();
        MM_INNER(As, Bs, acc, ty, tx);
        __syncthreads();
    }
    float rc = g_r[c], inv = g_invden[c];
    float* Sg = g_Sig + (size_t)c * Dd * Dd;
    for (int r = 0; r < 4; r++) {
        int i = bi * 64 + ty * 4 + r;
        float mui = g_mu[c * Dd + i];
        for (int q = 0; q < 4; q++) {
            int j = bj * 64 + tx * 4 + q;
            float v = g_B[(size_t)i * Dd + j] + acc[r][q] - rc * mui * g_mu[c * Dd + j];
            Sg[(size_t)i * Dd + j] = v * inv;
        }
    }
}

// ---------------- batched blocked Cholesky ----------------
__global__ void k_chol_diag(int s) {
    int c = blockIdx.x, t = threadIdx.x;
    float* A = g_Sig + (size_t)c * Dd * Dd;
    __shared__ float Ld[64][65];
    for (int idx = t; idx < 64 * 64; idx += 256) {
        int r = idx >> 6, k = idx & 63;
        Ld[r][k] = A[(size_t)(s * 64 + r) * Dd + s * 64 + k];
    }
    __syncthreads();
    for (int j = 0; j < 64; j++) {
        if (t == 0) Ld[j][j] = sqrtf(Ld[j][j]);
        __syncthreads();
        float dinv = 1.0f / Ld[j][j];
        if (t > j && t < 64) Ld[t][j] *= dinv;
        __syncthreads();
        int k = j + 1 + t;
        if (k < 64) {
            float lkj = Ld[k][j];
            for (int r = k; r < 64; r++) Ld[r][k] -= Ld[r][j] * lkj;
        }
        __syncthreads();
    }
    for (int idx = t; idx < 64 * 64; idx += 256) {
        int r = idx >> 6, k = idx & 63;
        if (k <= r) A[(size_t)(s * 64 + r) * Dd + s * 64 + k] = Ld[r][k];
    }
}

__global__ void k_chol_panel(int s) {
    int c = blockIdx.x, t = threadIdx.x;
    float* A = g_Sig + (size_t)c * Dd * Dd;
    __shared__ float Ld[64][64];
    __shared__ float zsh[64][128];
    for (int idx = t; idx < 64 * 64; idx += 128) {
        int r = idx >> 6, k = idx & 63;
        Ld[r][k] = A[(size_t)(s * 64 + r) * Dd + s * 64 + k];
    }
    __syncthreads();
    int g = 64 * (s + 1) + blockIdx.y * 128 + t;
    if (g < Dd) {
        float* row = A + (size_t)g * Dd + s * 64;
        for (int j = 0; j < 64; j++) {
            float acc = row[j];
            for (int k = 0; k < j; k++) acc -= Ld[j][k] * zsh[k][t];
            float v = acc / Ld[j][j];
            zsh[j][t] = v;
            row[j] = v;
        }
    }
}

__global__ void k_chol_syrk(int s) {
    int r0 = 64 * (s + 1);
    int bi = blockIdx.x, bj = blockIdx.y, c = blockIdx.z;
    if (bj > bi) return;
    int tid = threadIdx.x, tx = tid & 15, ty = tid >> 4;
    float* A = g_Sig + (size_t)c * Dd * Dd;
    int i0 = r0 + bi * 64, j0 = r0 + bj * 64;
    __shared__ float As[16 * 64], Bs[16 * 64];
    float acc[4][4] = {};
    for (int kt = 0; kt < 4; kt++) {
        mm_loadNT(As, A, i0, s * 64 + kt * 16, Dd, tid);
        mm_loadNT(Bs, A, j0, s * 64 + kt * 16, Dd, tid);
        __syncthreads();
        MM_INNER(As, Bs, acc, ty, tx);
        __syncthreads();
    }
    for (int r = 0; r < 4; r++) {
        int i = i0 + ty * 4 + r;
        for (int q = 0; q < 4; q++) {
            int j = j0 + tx * 4 + q;
            A[(size_t)i * Dd + j] -= acc[r][q];
        }
    }
}

// ---------------- TRTRI: U = L^{-1}, blocked solve on identity ----------------
__global__ void k_initI() {
    size_t t = (size_t)blockIdx.x * 256 + threadIdx.x;
    size_t ij = t & (size_t)(Dd * Dd - 1);
    int i = (int)(ij >> 10), j = (int)(ij & 1023);
    g_U[t] = (i == j) ? 1.0f : 0.0f;
}

__global__ void k_tri_solve(int s) {
    int c = blockIdx.x, t = threadIdx.x;
    const float* A = g_Sig + (size_t)c * Dd * Dd;
    __shared__ float Ld[64][64];
    __shared__ float zsh[64][128];
    for (int idx = t; idx < 64 * 64; idx += 128) {
        int r = idx >> 6, k = idx & 63;
        Ld[r][k] = A[(size_t)(s * 64 + r) * Dd + s * 64 + k];
    }
    __syncthreads();
    int jcol = blockIdx.y * 128 + t;
    float* Dp = g_U + ((size_t)c * Dd + s * 64) * Dd + jcol;
    for (int r = 0; r < 64; r++) {
        float acc = Dp[(size_t)r * Dd];
        for (int k = 0; k < r; k++) acc -= Ld[r][k] * zsh[k][t];
        float v = acc / Ld[r][r];
        zsh[r][t] = v;
        Dp[(size_t)r * Dd] = v;
    }
}

__global__ void k_tri_upd(int s) {
    int c = blockIdx.z;
    int i0 = 64 * (s + 1) + blockIdx.x * 64;
    int j0 = blockIdx.y * 64;
    int tid = threadIdx.x, tx = tid & 15, ty = tid >> 4;
    const float* A = g_Sig + (size_t)c * Dd * Dd;
    float* Dp = g_U + (size_t)c * Dd * Dd;
    __shared__ float As[16 * 64], Bs[16 * 64];
    float acc[4][4] = {};
    for (int kt = 0; kt < 4; kt++) {
        mm_loadNT(As, A, i0, s * 64 + kt * 16, Dd, tid);
        mm_loadT(Bs, Dp, s * 64 + kt * 16, j0, Dd, tid);
        __syncthreads();
        MM_INNER(As, Bs, acc, ty, tx);
        __syncthreads();
    }
    for (int r = 0; r < 4; r++) {
        float4* p = reinterpret_cast<float4*>(Dp + (size_t)(i0 + ty * 4 + r) * Dd + j0 + tx * 4);
        float4 v = *p;
        v.x -= acc[r][0]; v.y -= acc[r][1]; v.z -= acc[r][2]; v.w -= acc[r][3];
        *p = v;
    }
}

// ---------------- bf16 splits ----------------
__global__ void k_splitU() {
    size_t t = (size_t)blockIdx.x * 256 + threadIdx.x;
    float x = g_U[t];
    __nv_bfloat16 h = __float2bfloat16(x);
    g_Uh[t] = h;
    g_Ul[t] = __float2bfloat16(x - __bfloat162float(h));
}
__global__ void k_splitX(const float* __restrict__ Xq) {
    size_t t = (size_t)blockIdx.x * 256 + threadIdx.x;
    float x = Xq[t];
    __nv_bfloat16 h = __float2bfloat16(x);
    g_Xh[t] = h;
    g_Xl[t] = __float2bfloat16(x - __bfloat162float(h));
}

// v_c = U_c mu_c
__global__ void k_v() {
    int d = blockIdx.x, c = blockIdx.y, t = threadIdx.x;
    __shared__ float red[128];
    const float* Ur = g_U + ((size_t)c * Dd + d) * Dd;
    const float* mu = g_mu + c * Dd;
    float a = 0.f;
    for (int e = t; e < Dd; e += 128) a += Ur[e] * mu[e];
    red[t] = a; __syncthreads();
    for (int st = 64; st; st >>= 1) { if (t < st) red[t] += red[t + st]; __syncthreads(); }
    if (t == 0) g_v[c * Dd + d] = red[0];
}

// dn2[m][c] = ||xq||^2 - 2 xq.mu_c + ||mu_c||^2
__global__ void k_dn(const float* __restrict__ Xq) {
    int m = blockIdx.x, t = threadIdx.x;
    __shared__ float red[17][129];
    float dc[16];
#pragma unroll
    for (int c = 0; c < 16; c++) dc[c] = 0.f;
    float s2 = 0.f;
    for (int i = 0; i < 8; i++) {
        int d = t + i * 128;
        float x = Xq[(size_t)m * Dd + d];
        s2 += x * x;
#pragma unroll
        for (int c = 0; c < 16; c++) dc[c] += x * g_mu[c * Dd + d];
    }
#pragma unroll
    for (int c = 0; c < 16; c++) red[c][t] = dc[c];
    red[16][t] = s2;
    __syncthreads();
    for (int st = 64; st; st >>= 1) {
        if (t < st) {
#pragma unroll
            for (int r = 0; r < 17; r++) red[r][t] += red[r][t + st];
        }
        __syncthreads();
    }
    if (t < 16)
        g_dn2[(size_t)m * Cc + t] = red[16][0] - 2.f * red[t][0] + g_mun[t];
}

// ---------------- fused mma.sync kernel: q = ||U_c Xq^T - v_c||^2 -> logits ----
// grid (Mq/128, Cc), 256 threads (8 warps, 4x2), dyn smem 128 KB
// smem per stage (64 KB): Uh[128][64] Ul Xh Xl, 16 KB each, 16B-chunk XOR swizzle
#define STAGE_BYTES 65536
#define TILE_BYTES  16384
#define SM_FUSED_TOTAL (2*STAGE_BYTES)

extern "C" __global__ void __launch_bounds__(256, 1)
k_fused(float* __restrict__ out) {
    extern __shared__ char sm[];
    uint32_t smb = smem_u32(sm);
    int tid = threadIdx.x;
    int wid = tid >> 5, lid = tid & 31;
    int wr = wid >> 1, wc = wid & 1;       // 4x2 warps
    int sub = lid >> 3, r8 = lid & 7;
    int m0 = blockIdx.x * 128;
    int c = blockIdx.y;

    const __nv_bfloat16* Ah = g_Uh + ((size_t)c << 20);
    const __nv_bfloat16* Al = g_Ul + ((size_t)c << 20);

    float acc[2][8][4];
#pragma unroll
    for (int a = 0; a < 2; a++)
#pragma unroll
        for (int b = 0; b < 8; b++)
#pragma unroll
            for (int d = 0; d < 4; d++) acc[a][b][d] = 0.f;
    float qpart[16];
#pragma unroll
    for (int i = 0; i < 16; i++) qpart[i] = 0.f;

    // precompute per-lane ldmatrix row geometry
    int arow_base0 = wr * 32 + (sub & 1) * 8 + r8;       // + mf*16
    int acko = sub >> 1;
    int brow_base = (sub >> 1) * 8 + r8;                 // + nf2*16
    int bcko = sub & 1;

    for (int dt = 0; dt < 8; dt++) {
        int nb = (dt + 1) * 2;   // K chunks of 64
        // prefetch kb=0
        {
            uint32_t sb = smb;
            for (int idx = tid; idx < 1024; idx += 256) {
                int row = idx >> 3, ch = idx & 7;
                uint32_t dsw = row * 128 + ((ch ^ (row & 7)) << 4);
                size_t gu = (size_t)(dt * 128 + row) * Dd + ch * 8;
                size_t gx = (size_t)(m0 + row) * Dd + ch * 8;
                cpa16(sb + dsw, Ah + gu);
                cpa16(sb + TILE_BYTES + dsw, Al + gu);
                cpa16(sb + 2 * TILE_BYTES + dsw, g_Xh + gx);
                cpa16(sb + 3 * TILE_BYTES + dsw, g_Xl + gx);
            }
            cpa_commit();
        }
        for (int kb = 0; kb < nb; kb++) {
            int st = kb & 1;
            if (kb + 1 < nb) {
                uint32_t sb = smb + (st ^ 1) * STAGE_BYTES;
                int k0 = (kb + 1) * 64;
                for (int idx = tid; idx < 1024; idx += 256) {
                    int row = idx >> 3, ch = idx & 7;
                    uint32_t dsw = row * 128 + ((ch ^ (row & 7)) << 4);
                    size_t gu = (size_t)(dt * 128 + row) * Dd + k0 + ch * 8;
                    size_t gx = (size_t)(m0 + row) * Dd + k0 + ch * 8;
                    cpa16(sb + dsw, Ah + gu);
                    cpa16(sb + TILE_BYTES + dsw, Al + gu);
                    cpa16(sb + 2 * TILE_BYTES + dsw, g_Xh + gx);
                    cpa16(sb + 3 * TILE_BYTES + dsw, g_Xl + gx);
                }
                cpa_commit();
                cpa_wait1();
            } else {
                cpa_wait0();
            }
            __syncthreads();

            uint32_t uhb = smb + st * STAGE_BYTES;
            uint32_t ulb = uhb + TILE_BYTES;
            uint32_t xhb = uhb + 2 * TILE_BYTES;
            uint32_t xlb = uhb + 3 * TILE_BYTES;
#pragma unroll
            for (int ks = 0; ks < 4; ks++) {
                int k2 = ks * 2;
                uint32_t ah[2][4], al2[2][4], bh[4][4], bl[4][4];
#pragma unroll
                for (int mf = 0; mf < 2; mf++) {
                    int row = arow_base0 + mf * 16;
                    uint32_t off = row * 128 + (((k2 + acko) ^ (row & 7)) << 4);
                    ldm_x4(ah[mf], uhb + off);
                    ldm_x4(al2[mf], ulb + off);
                }
#pragma unroll
                for (int nf2 = 0; nf2 < 4; nf2++) {
                    int row = brow_base + (wc * 64 + nf2 * 16);
                    uint32_t off = row * 128 + (((k2 + bcko) ^ (row & 7)) << 4);
                    ldm_x4(bh[nf2], xhb + off);
                    ldm_x4(bl[nf2], xlb + off);
                }
#pragma unroll
                for (int mf = 0; mf < 2; mf++) {
#pragma unroll
                    for (int nf = 0; nf < 8; nf++) {
                        uint32_t b0h = bh[nf >> 1][(nf & 1) * 2];
                        uint32_t b1h = bh[nf >> 1][(nf & 1) * 2 + 1];
                        uint32_t b0l = bl[nf >> 1][(nf & 1) * 2];
                        uint32_t b1l = bl[nf >> 1][(nf & 1) * 2 + 1];
                        mma_bf16(acc[mf][nf], ah[mf], b0h, b1h);
                        mma_bf16(acc[mf][nf], ah[mf], b0l, b1l);
                        mma_bf16(acc[mf][nf], al2[mf], b0h, b1h);
                    }
                }
            }
            __syncthreads();
        }
        // epilogue for this d-row-block: subtract v, square, fold into qpart
#pragma unroll
        for (int mf = 0; mf < 2; mf++) {
            int dg = dt * 128 + wr * 32 + mf * 16 + (lid >> 2);
            float v0 = g_v[c * Dd + dg];
            float v1 = g_v[c * Dd + dg + 8];
#pragma unroll
            for (int nf = 0; nf < 8; nf++) {
                float z;
                z = acc[mf][nf][0] - v0; qpart[nf * 2 + 0] += z * z;
                z = acc[mf][nf][1] - v0; qpart[nf * 2 + 1] += z * z;
                z = acc[mf][nf][2] - v1; qpart[nf * 2 + 0] += z * z;
                z = acc[mf][nf][3] - v1; qpart[nf * 2 + 1] += z * z;
                acc[mf][nf][0] = 0.f; acc[mf][nf][1] = 0.f;
                acc[mf][nf][2] = 0.f; acc[mf][nf][3] = 0.f;
            }
        }
    }

    // deterministic cross-thread reduction: red[col][contrib]
    __syncthreads();
    float* red = reinterpret_cast<float*>(sm);   // 128*33 floats = 16.9 KB
#pragma unroll
    for (int nf = 0; nf < 8; nf++) {
#pragma unroll
        for (int b = 0; b < 2; b++) {
            int col = wc * 64 + nf * 8 + (lid & 3) * 2 + b;
            red[col * 33 + wr * 8 + (lid >> 2)] = qpart[nf * 2 + b];
        }
    }
    __syncthreads();
    if (tid < 128) {
        float q = 0.f;
#pragma unroll
        for (int i = 0; i < 32; i++) q += red[tid * 33 + i];
        int m = m0 + tid;
        out[(size_t)m * Cc + c] = -((1.0f - REGC) * q + REGC * g_dn2[(size_t)m * Cc + c]);
    }
}

// ---------------- orchestration ----------------
extern "C" void kernel_launch(void* const* d_in, const int* in_sizes, int n_in,
                              void* d_out, int out_size) {
    const float* X     = (const float*)d_in[0];
    const int*   y     = (const int*)d_in[1];
    const float* Xq    = (const float*)d_in[2];
    const float* m     = (const float*)d_in[3];
    const float* kappa = (const float*)d_in[4];
    const float* nu    = (const float*)d_in[5];
    const float* tdiag = (const float*)d_in[6];
    const float* tlow  = (const float*)d_in[7];
    float* out = (float*)d_out;

    cudaFuncSetAttribute((const void*)k_fused,
                         cudaFuncAttributeMaxDynamicSharedMemorySize, SM_FUSED_TOTAL);

    k_gather<<<1, Cc>>>(y);
    k_scalars<<<1, Cc>>>(kappa, nu);
    k_mu<<<dim3(Cc, Dd / 256), 256>>>(X, m, kappa);
    k_mun<<<Cc, 256>>>();
    k_buildL<<<(Dd * Dd) / 256, 256>>>(tdiag, tlow);
    k_base<<<dim3(16, 16), 256>>>(m, kappa);
    k_sigma<<<dim3(16, 16, Cc), 256>>>(X);

    for (int s = 0; s < NSTEP; s++) {
        k_chol_diag<<<Cc, 256>>>(s);
        int rows = Dd - 64 * (s + 1);
        if (rows > 0) {
            k_chol_panel<<<dim3(Cc, (rows + 127) / 128), 128>>>(s);
            int nb = rows / 64;
            k_chol_syrk<<<dim3(nb, nb, Cc), 256>>>(s);
        }
    }

    // TRTRI
    k_initI<<<(int)(((size_t)Cc * Dd * Dd) / 256), 256>>>();
    for (int s = 0; s < NSTEP; s++) {
        int ncol = ((s + 1) * 64 + 127) / 128;
        k_tri_solve<<<dim3(Cc, ncol), 128>>>(s);
        int rows = Dd - 64 * (s + 1);
        if (rows > 0)
            k_tri_upd<<<dim3(rows / 64, s + 1, Cc), 256>>>(s);
    }

    k_splitU<<<(int)(((size_t)Cc * Dd * Dd) / 256), 256>>>();
    k_splitX<<<(int)(((size_t)Mq * Dd) / 256), 256>>>(Xq);
    k_v<<<dim3(Dd, Cc), 128>>>();
    k_dn<<<Mq, 128>>>(Xq);

    k_fused<<<dim3(Mq / 128, Cc), 256, SM_FUSED_TOTAL>>>(out);
}

// round 5
// speedup vs baseline: 1.5744x; 1.2305x over previous
#include <cuda_runtime.h>
#include <cuda_bf16.h>
#include <math.h>
#include <stdint.h>

#define Ncnt 4096
#define Dd   1024
#define Mq   4096
#define Cc   16
#define REGC 0.1f

// ---------------- scratch ----------------
__device__ int   g_cnt[Cc];
__device__ int   g_off[Cc];
__device__ int   g_idx[Ncnt];
__device__ float g_r[Cc];
__device__ float g_invden[Cc];
__device__ float g_mu[Cc*Dd];
__device__ float g_mun[Cc];
__device__ float g_L[Dd*Dd];
__device__ float g_B[Dd*Dd];
__device__ float g_Sig[(size_t)Cc*Dd*Dd];
__device__ float g_U[(size_t)Cc*Dd*Dd];
__device__ float g_T[(size_t)Cc*512*512];
__device__ __nv_bfloat16 g_Uh[(size_t)Cc*Dd*Dd];
__device__ __nv_bfloat16 g_Ul[(size_t)Cc*Dd*Dd];
__device__ __nv_bfloat16 g_Xh[(size_t)Mq*Dd];
__device__ __nv_bfloat16 g_Xl[(size_t)Mq*Dd];
__device__ float g_v[Cc*Dd];
__device__ float g_dn2[(size_t)Mq*Cc];

// ---------------- helpers ----------------
__device__ __forceinline__ uint32_t smem_u32(const void* p) {
    uint32_t a;
    asm("{ .reg .u64 t; cvta.to.shared.u64 t, %1; cvt.u32.u64 %0, t; }" : "=r"(a) : "l"(p));
    return a;
}
__device__ __forceinline__ void cpa16(uint32_t dst, const void* src) {
    asm volatile("cp.async.cg.shared.global [%0], [%1], 16;" :: "r"(dst), "l"(src) : "memory");
}
__device__ __forceinline__ void cpa_commit() { asm volatile("cp.async.commit_group;" ::: "memory"); }
__device__ __forceinline__ void cpa_wait0()  { asm volatile("cp.async.wait_group 0;" ::: "memory"); }
__device__ __forceinline__ void cpa_wait1()  { asm volatile("cp.async.wait_group 1;" ::: "memory"); }
__device__ __forceinline__ void ldm_x4(uint32_t* r, uint32_t a) {
    asm volatile("ldmatrix.sync.aligned.m8n8.x4.shared.b16 {%0,%1,%2,%3}, [%4];"
        : "=r"(r[0]), "=r"(r[1]), "=r"(r[2]), "=r"(r[3]) : "r"(a));
}
__device__ __forceinline__ void mma_bf16(float* c, const uint32_t* a, uint32_t b0, uint32_t b1) {
    asm volatile("mma.sync.aligned.m16n8k16.row.col.f32.bf16.bf16.f32 "
        "{%0,%1,%2,%3}, {%4,%5,%6,%7}, {%8,%9}, {%0,%1,%2,%3};"
        : "+f"(c[0]), "+f"(c[1]), "+f"(c[2]), "+f"(c[3])
        : "r"(a[0]), "r"(a[1]), "r"(a[2]), "r"(a[3]), "r"(b0), "r"(b1));
}

// ---------------- fit-side small kernels ----------------
__global__ void k_gather(const int* __restrict__ y) {
    int c = threadIdx.x;
    if (c >= Cc) return;
    int cnt = 0;
    for (int i = 0; i < Ncnt; i++) cnt += (y[i] == c);
    g_cnt[c] = cnt;
    __syncthreads();
    int off = 0;
    for (int cc = 0; cc < c; cc++) off += g_cnt[cc];
    g_off[c] = off;
    int p = off;
    for (int i = 0; i < Ncnt; i++) if (y[i] == c) g_idx[p++] = i;
}

__global__ void k_scalars(const float* __restrict__ kappa, const float* __restrict__ nu) {
    int c = threadIdx.x;
    if (c >= Cc) return;
    float kap = fabsf(kappa[0]) + 1e-6f;
    float nu_ = fmaxf(nu[0], (float)Dd - 1.0f + 1e-6f);
    float Nj  = (float)g_cnt[c];
    g_r[c]      = kap + Nj;
    g_invden[c] = 1.0f / (nu_ + Nj + (float)Dd + 2.0f);
}

__global__ void k_mu(const float* __restrict__ X, const float* __restrict__ m,
                     const float* __restrict__ kappa) {
    int c = blockIdx.x;
    int j = blockIdx.y * 256 + threadIdx.x;
    int cnt = g_cnt[c], off = g_off[c];
    float s = 0.f;
    for (int k = 0; k < cnt; k++) s += X[(size_t)g_idx[off + k] * Dd + j];
    float kap = fabsf(kappa[0]) + 1e-6f;
    g_mu[c * Dd + j] = (kap * m[j] + s) / (kap + (float)cnt);
}

__global__ void k_mun() {
    int c = blockIdx.x, t = threadIdx.x;
    __shared__ float red[256];
    float a = 0.f;
    for (int d = t; d < Dd; d += 256) { float v = g_mu[c * Dd + d]; a += v * v; }
    red[t] = a; __syncthreads();
    for (int st = 128; st; st >>= 1) { if (t < st) red[t] += red[t + st]; __syncthreads(); }
    if (t == 0) g_mun[c] = red[0];
}

__global__ void k_buildL(const float* __restrict__ tdiag, const float* __restrict__ tlow) {
    int t = blockIdx.x * 256 + threadIdx.x;
    int i = t / Dd, j = t % Dd;
    float v;
    if (i == j)      v = fabsf(tdiag[i]);
    else if (i > j)  v = tlow[t];
    else             v = 0.f;
    g_L[t] = v;
}

// ---------------- SIMT GEMM tile helpers ----------------
__device__ __forceinline__ void mm_loadNT(float* sm, const float* __restrict__ G,
                                          int row0, int k0, int ld, int tid) {
    int i = tid >> 2;
    int q = (tid & 3) * 4;
    float4 v = *reinterpret_cast<const float4*>(G + (size_t)(row0 + i) * ld + k0 + q);
    sm[(q + 0) * 64 + i] = v.x;
    sm[(q + 1) * 64 + i] = v.y;
    sm[(q + 2) * 64 + i] = v.z;
    sm[(q + 3) * 64 + i] = v.w;
}
__device__ __forceinline__ void mm_loadT(float* sm, const float* __restrict__ G,
                                         int k0, int col0, int ld, int tid) {
    int kk = tid >> 4;
    int j  = (tid & 15) * 4;
    float4 v = *reinterpret_cast<const float4*>(G + (size_t)(k0 + kk) * ld + col0 + j);
    *reinterpret_cast<float4*>(sm + kk * 64 + j) = v;
}

#define MM_INNER(As, Bs, acc, ty, tx)                                     \
    _Pragma("unroll")                                                     \
    for (int kk = 0; kk < 16; kk++) {                                     \
        float4 a = *reinterpret_cast<float4*>((As) + kk * 64 + (ty) * 4); \
        float4 b = *reinterpret_cast<float4*>((Bs) + kk * 64 + (tx) * 4); \
        acc[0][0] += a.x * b.x; acc[0][1] += a.x * b.y;                   \
        acc[0][2] += a.x * b.z; acc[0][3] += a.x * b.w;                   \
        acc[1][0] += a.y * b.x; acc[1][1] += a.y * b.y;                   \
        acc[1][2] += a.y * b.z; acc[1][3] += a.y * b.w;                   \
        acc[2][0] += a.z * b.x; acc[2][1] += a.z * b.y;                   \
        acc[2][2] += a.z * b.z; acc[2][3] += a.z * b.w;                   \
        acc[3][0] += a.w * b.x; acc[3][1] += a.w * b.y;                   \
        acc[3][2] += a.w * b.z; acc[3][3] += a.w * b.w;                   \
    }

__global__ void k_base(const float* __restrict__ m, const float* __restrict__ kappa) {
    int bi = blockIdx.x, bj = blockIdx.y;
    if (bj > bi) return;
    int tid = threadIdx.x, tx = tid & 15, ty = tid >> 4;
    __shared__ float As[16 * 64], Bs[16 * 64];
    float acc[4][4] = {};
    int kchunks = (bj + 1) * 4;
    for (int kt = 0; kt < kchunks; kt++) {
        mm_loadNT(As, g_L, bi * 64, kt * 16, Dd, tid);
        mm_loadNT(Bs, g_L, bj * 64, kt * 16, Dd, tid);
        __syncthreads();
        MM_INNER(As, Bs, acc, ty, tx);
        __syncthreads();
    }
    float kap = fabsf(kappa[0]) + 1e-6f;
    for (int r = 0; r < 4; r++) {
        int i = bi * 64 + ty * 4 + r;
        for (int q = 0; q < 4; q++) {
            int j = bj * 64 + tx * 4 + q;
            g_B[(size_t)i * Dd + j] = acc[r][q] + kap * m[i] * m[j];
        }
    }
}

__global__ void k_sigma(const float* __restrict__ X) {
    int bi = blockIdx.x, bj = blockIdx.y, c = blockIdx.z;
    if (bj > bi) return;
    int tid = threadIdx.x, tx = tid & 15, ty = tid >> 4;
    int cnt = g_cnt[c], off = g_off[c];
    __shared__ float As[16 * 64], Bs[16 * 64];
    float acc[4][4] = {};
    int kk = tid >> 4;
    int jj = (tid & 15) * 4;
    for (int kt = 0; kt < cnt; kt += 16) {
        int krow = kt + kk;
        float4 va = make_float4(0.f, 0.f, 0.f, 0.f), vb = va;
        if (krow < cnt) {
            const float* row = X + (size_t)g_idx[off + krow] * Dd;
            va = *reinterpret_cast<const float4*>(row + bi * 64 + jj);
            vb = *reinterpret_cast<const float4*>(row + bj * 64 + jj);
        }
        *reinterpret_cast<float4*>(As + kk * 64 + jj) = va;
        *reinterpret_cast<float4*>(Bs + kk * 64 + jj) = vb;
        __syncthreads();
        MM_INNER(As, Bs, acc, ty, tx);
        __syncthreads();
    }
    float rc = g_r[c], inv = g_invden[c];
    float* Sg = g_Sig + (size_t)c * Dd * Dd;
    for (int r = 0; r < 4; r++) {
        int i = bi * 64 + ty * 4 + r;
        float mui = g_mu[c * Dd + i];
        for (int q = 0; q < 4; q++) {
            int j = bj * 64 + tx * 4 + q;
            float v = g_B[(size_t)i * Dd + j] + acc[r][q] - rc * mui * g_mu[c * Dd + j];
            Sg[(size_t)i * Dd + j] = v * inv;
        }
    }
}

// ---------------- Cholesky: merged diag+panel step, then SYRK ----------------
__global__ void k_chol_step(int s) {
    int c = blockIdx.x, t = threadIdx.x;   // 128 threads
    float* A = g_Sig + (size_t)c * Dd * Dd;
    __shared__ float Ld[64][65];
    __shared__ float zsh[64][128];
    for (int idx = t; idx < 64 * 64; idx += 128) {
        int r = idx >> 6, k = idx & 63;
        Ld[r][k] = A[(size_t)(s * 64 + r) * Dd + s * 64 + k];
    }
    __syncthreads();
    for (int j = 0; j < 64; j++) {
        if (t == 0) Ld[j][j] = sqrtf(Ld[j][j]);
        __syncthreads();
        float dinv = 1.0f / Ld[j][j];
        if (t > j && t < 64) Ld[t][j] *= dinv;
        __syncthreads();
        int k = j + 1 + t;
        if (k < 64) {
            float lkj = Ld[k][j];
            for (int r = k; r < 64; r++) Ld[r][k] -= Ld[r][j] * lkj;
        }
        __syncthreads();
    }
    if (blockIdx.y == 0) {
        for (int idx = t; idx < 64 * 64; idx += 128) {
            int r = idx >> 6, k = idx & 63;
            if (k <= r) A[(size_t)(s * 64 + r) * Dd + s * 64 + k] = Ld[r][k];
        }
    }
    int g = 64 * (s + 1) + blockIdx.y * 128 + t;
    if (g < Dd) {
        float* row = A + (size_t)g * Dd + s * 64;
        for (int j = 0; j < 64; j++) {
            float acc = row[j];
            for (int k = 0; k < j; k++) acc -= Ld[j][k] * zsh[k][t];
            float v = acc / Ld[j][j];
            zsh[j][t] = v;
            row[j] = v;
        }
    }
}

__global__ void k_chol_syrk(int s) {
    int r0 = 64 * (s + 1);
    int bi = blockIdx.x, bj = blockIdx.y, c = blockIdx.z;
    if (bj > bi) return;
    int tid = threadIdx.x, tx = tid & 15, ty = tid >> 4;
    float* A = g_Sig + (size_t)c * Dd * Dd;
    int i0 = r0 + bi * 64, j0 = r0 + bj * 64;
    __shared__ float As[16 * 64], Bs[16 * 64];
    float acc[4][4] = {};
    for (int kt = 0; kt < 4; kt++) {
        mm_loadNT(As, A, i0, s * 64 + kt * 16, Dd, tid);
        mm_loadNT(Bs, A, j0, s * 64 + kt * 16, Dd, tid);
        __syncthreads();
        MM_INNER(As, Bs, acc, ty, tx);
        __syncthreads();
    }
    for (int r = 0; r < 4; r++) {
        int i = i0 + ty * 4 + r;
        for (int q = 0; q < 4; q++) {
            int j = j0 + tx * 4 + q;
            A[(size_t)i * Dd + j] -= acc[r][q];
        }
    }
}

// ---------------- TRTRI by recursive doubling ----------------
__global__ void k_initI() {
    size_t t = (size_t)blockIdx.x * 256 + threadIdx.x;
    size_t ij = t & (size_t)(Dd * Dd - 1);
    int i = (int)(ij >> 10), j = (int)(ij & 1023);
    g_U[t] = (i == j) ? 1.0f : 0.0f;
}

// invert all 64x64 diag blocks; one block per (diagblock, class), 64 threads
__global__ void k_inv_diag() {
    int b = blockIdx.x, c = blockIdx.y, t = threadIdx.x;
    const float* A = g_Sig + (size_t)c * Dd * Dd;
    float* Up = g_U + (size_t)c * Dd * Dd;
    __shared__ float Ld[64][65];
    __shared__ float V[64][65];
    for (int idx = t; idx < 64 * 64; idx += 64) {
        int r = idx >> 6, k = idx & 63;
        Ld[r][k] = A[(size_t)(b * 64 + r) * Dd + b * 64 + k];
    }
    __syncthreads();
    // thread t solves column t: L v = e_t (independent columns, no syncs)
    for (int r = 0; r < t; r++) V[r][t] = 0.f;
    for (int r = t; r < 64; r++) {
        float acc = (r == t) ? 1.f : 0.f;
        for (int k = t; k < r; k++) acc -= Ld[r][k] * V[k][t];
        V[r][t] = acc / Ld[r][r];
    }
    __syncthreads();
    for (int idx = t; idx < 64 * 64; idx += 64) {
        int r = idx >> 6, k = idx & 63;
        Up[(size_t)(b * 64 + r) * Dd + b * 64 + k] = V[r][k];
    }
}

// level-combine GEMMs. mode 0: T = L21 * U_A ; mode 1: U21 = -U_C * T
__global__ void k_rec(int s, int mode) {
    int p = Dd / (2 * s);
    int bi = blockIdx.x, bj = blockIdx.y;
    int pair = blockIdx.z % p, c = blockIdx.z / p;
    int tid = threadIdx.x, tx = tid & 15, ty = tid >> 4;
    int rA = pair * 2 * s, rC = rA + s;
    const float* Sg = g_Sig + (size_t)c * Dd * Dd;
    float* Up = g_U + (size_t)c * Dd * Dd;
    float* T = g_T + (size_t)c * 512 * 512 + (size_t)pair * s * s;
    __shared__ float As[16 * 64], Bs[16 * 64];
    float acc[4][4] = {};
    if (mode == 0) {
        // k range: [bj*64, s) since U_A[k][j]=0 for k < j
        for (int kt = bj * 4; kt < s / 16; kt++) {
            mm_loadNT(As, Sg + (size_t)(rC + bi * 64) * Dd + rA, 0, kt * 16, Dd, tid);
            mm_loadT(Bs, Up + (size_t)rA * Dd + rA + bj * 64, kt * 16, 0, Dd, tid);
            __syncthreads();
            MM_INNER(As, Bs, acc, ty, tx);
            __syncthreads();
        }
        for (int r = 0; r < 4; r++)
            for (int q = 0; q < 4; q++)
                T[(size_t)(bi * 64 + ty * 4 + r) * s + bj * 64 + tx * 4 + q] = acc[r][q];
    } else {
        // k range: [0, (bi+1)*64) since U_C[i][k]=0 for k > i
        for (int kt = 0; kt < (bi + 1) * 4; kt++) {
            mm_loadNT(As, Up + (size_t)(rC + bi * 64) * Dd + rC, 0, kt * 16, Dd, tid);
            mm_loadT(Bs, T + bj * 64, kt * 16, 0, s, tid);
            __syncthreads();
            MM_INNER(As, Bs, acc, ty, tx);
            __syncthreads();
        }
        for (int r = 0; r < 4; r++)
            for (int q = 0; q < 4; q++)
                Up[(size_t)(rC + bi * 64 + ty * 4 + r) * Dd + rA + bj * 64 + tx * 4 + q] = -acc[r][q];
    }
}

// ---------------- bf16 splits ----------------
__global__ void k_splitU() {
    size_t t = (size_t)blockIdx.x * 256 + threadIdx.x;
    float x = g_U[t];
    __nv_bfloat16 h = __float2bfloat16(x);
    g_Uh[t] = h;
    g_Ul[t] = __float2bfloat16(x - __bfloat162float(h));
}
__global__ void k_splitX(const float* __restrict__ Xq) {
    size_t t = (size_t)blockIdx.x * 256 + threadIdx.x;
    float x = Xq[t];
    __nv_bfloat16 h = __float2bfloat16(x);
    g_Xh[t] = h;
    g_Xl[t] = __float2bfloat16(x - __bfloat162float(h));
}

// v_c = U_c mu_c  (triangular extent)
__global__ void k_v() {
    int d = blockIdx.x, c = blockIdx.y, t = threadIdx.x;
    __shared__ float red[128];
    const float* Ur = g_U + ((size_t)c * Dd + d) * Dd;
    const float* mu = g_mu + c * Dd;
    float a = 0.f;
    for (int e = t; e <= d; e += 128) a += Ur[e] * mu[e];
    red[t] = a; __syncthreads();
    for (int st = 64; st; st >>= 1) { if (t < st) red[t] += red[t + st]; __syncthreads(); }
    if (t == 0) g_v[c * Dd + d] = red[0];
}

__global__ void k_dn(const float* __restrict__ Xq) {
    int m = blockIdx.x, t = threadIdx.x;
    __shared__ float red[17][129];
    float dc[16];
#pragma unroll
    for (int c = 0; c < 16; c++) dc[c] = 0.f;
    float s2 = 0.f;
    for (int i = 0; i < 8; i++) {
        int d = t + i * 128;
        float x = Xq[(size_t)m * Dd + d];
        s2 += x * x;
#pragma unroll
        for (int c = 0; c < 16; c++) dc[c] += x * g_mu[c * Dd + d];
    }
#pragma unroll
    for (int c = 0; c < 16; c++) red[c][t] = dc[c];
    red[16][t] = s2;
    __syncthreads();
    for (int st = 64; st; st >>= 1) {
        if (t < st) {
#pragma unroll
            for (int r = 0; r < 17; r++) red[r][t] += red[r][t + st];
        }
        __syncthreads();
    }
    if (t < 16)
        g_dn2[(size_t)m * Cc + t] = red[16][0] - 2.f * red[t][0] + g_mun[t];
}

// ---------------- fused mma.sync kernel ----------------
#define STAGE_BYTES 65536
#define TILE_BYTES  16384
#define SM_FUSED_TOTAL (2*STAGE_BYTES)

extern "C" __global__ void __launch_bounds__(256, 1)
k_fused(float* __restrict__ out) {
    extern __shared__ char sm[];
    uint32_t smb = smem_u32(sm);
    int tid = threadIdx.x;
    int wid = tid >> 5, lid = tid & 31;
    int wr = wid >> 1, wc = wid & 1;
    int sub = lid >> 3, r8 = lid & 7;
    int m0 = blockIdx.x * 128;
    int c = blockIdx.y;

    const __nv_bfloat16* Ah = g_Uh + ((size_t)c << 20);
    const __nv_bfloat16* Al = g_Ul + ((size_t)c << 20);

    float acc[2][8][4];
#pragma unroll
    for (int a = 0; a < 2; a++)
#pragma unroll
        for (int b = 0; b < 8; b++)
#pragma unroll
            for (int d = 0; d < 4; d++) acc[a][b][d] = 0.f;
    float qpart[16];
#pragma unroll
    for (int i = 0; i < 16; i++) qpart[i] = 0.f;

    int arow_base0 = wr * 32 + (sub & 1) * 8 + r8;
    int acko = sub >> 1;
    int brow_base = (sub >> 1) * 8 + r8;
    int bcko = sub & 1;

    for (int dt = 0; dt < 8; dt++) {
        int nb = (dt + 1) * 2;
        {
            uint32_t sb = smb;
            for (int idx = tid; idx < 1024; idx += 256) {
                int row = idx >> 3, ch = idx & 7;
                uint32_t dsw = row * 128 + ((ch ^ (row & 7)) << 4);
                size_t gu = (size_t)(dt * 128 + row) * Dd + ch * 8;
                size_t gx = (size_t)(m0 + row) * Dd + ch * 8;
                cpa16(sb + dsw, Ah + gu);
                cpa16(sb + TILE_BYTES + dsw, Al + gu);
                cpa16(sb + 2 * TILE_BYTES + dsw, g_Xh + gx);
                cpa16(sb + 3 * TILE_BYTES + dsw, g_Xl + gx);
            }
            cpa_commit();
        }
        for (int kb = 0; kb < nb; kb++) {
            int st = kb & 1;
            if (kb + 1 < nb) {
                uint32_t sb = smb + (st ^ 1) * STAGE_BYTES;
                int k0 = (kb + 1) * 64;
                for (int idx = tid; idx < 1024; idx += 256) {
                    int row = idx >> 3, ch = idx & 7;
                    uint32_t dsw = row * 128 + ((ch ^ (row & 7)) << 4);
                    size_t gu = (size_t)(dt * 128 + row) * Dd + k0 + ch * 8;
                    size_t gx = (size_t)(m0 + row) * Dd + k0 + ch * 8;
                    cpa16(sb + dsw, Ah + gu);
                    cpa16(sb + TILE_BYTES + dsw, Al + gu);
                    cpa16(sb + 2 * TILE_BYTES + dsw, g_Xh + gx);
                    cpa16(sb + 3 * TILE_BYTES + dsw, g_Xl + gx);
                }
                cpa_commit();
                cpa_wait1();
            } else {
                cpa_wait0();
            }
            __syncthreads();

            uint32_t uhb = smb + st * STAGE_BYTES;
            uint32_t ulb = uhb + TILE_BYTES;
            uint32_t xhb = uhb + 2 * TILE_BYTES;
            uint32_t xlb = uhb + 3 * TILE_BYTES;
#pragma unroll
            for (int ks = 0; ks < 4; ks++) {
                int k2 = ks * 2;
                uint32_t ah[2][4], al2[2][4], bh[4][4], bl[4][4];
#pragma unroll
                for (int mf = 0; mf < 2; mf++) {
                    int row = arow_base0 + mf * 16;
                    uint32_t off = row * 128 + (((k2 + acko) ^ (row & 7)) << 4);
                    ldm_x4(ah[mf], uhb + off);
                    ldm_x4(al2[mf], ulb + off);
                }
#pragma unroll
                for (int nf2 = 0; nf2 < 4; nf2++) {
                    int row = brow_base + (wc * 64 + nf2 * 16);
                    uint32_t off = row * 128 + (((k2 + bcko) ^ (row & 7)) << 4);
                    ldm_x4(bh[nf2], xhb + off);
                    ldm_x4(bl[nf2], xlb + off);
                }
#pragma unroll
                for (int mf = 0; mf < 2; mf++) {
#pragma unroll
                    for (int nf = 0; nf < 8; nf++) {
                        uint32_t b0h = bh[nf >> 1][(nf & 1) * 2];
                        uint32_t b1h = bh[nf >> 1][(nf & 1) * 2 + 1];
                        uint32_t b0l = bl[nf >> 1][(nf & 1) * 2];
                        uint32_t b1l = bl[nf >> 1][(nf & 1) * 2 + 1];
                        mma_bf16(acc[mf][nf], ah[mf], b0h, b1h);
                        mma_bf16(acc[mf][nf], ah[mf], b0l, b1l);
                        mma_bf16(acc[mf][nf], al2[mf], b0h, b1h);
                    }
                }
            }
            __syncthreads();
        }
#pragma unroll
        for (int mf = 0; mf < 2; mf++) {
            int dg = dt * 128 + wr * 32 + mf * 16 + (lid >> 2);
            float v0 = g_v[c * Dd + dg];
            float v1 = g_v[c * Dd + dg + 8];
#pragma unroll
            for (int nf = 0; nf < 8; nf++) {
                float z;
                z = acc[mf][nf][0] - v0; qpart[nf * 2 + 0] += z * z;
                z = acc[mf][nf][1] - v0; qpart[nf * 2 + 1] += z * z;
                z = acc[mf][nf][2] - v1; qpart[nf * 2 + 0] += z * z;
                z = acc[mf][nf][3] - v1; qpart[nf * 2 + 1] += z * z;
                acc[mf][nf][0] = 0.f; acc[mf][nf][1] = 0.f;
                acc[mf][nf][2] = 0.f; acc[mf][nf][3] = 0.f;
            }
        }
    }

    __syncthreads();
    float* red = reinterpret_cast<float*>(sm);
#pragma unroll
    for (int nf = 0; nf < 8; nf++) {
#pragma unroll
        for (int b = 0; b < 2; b++) {
            int col = wc * 64 + nf * 8 + (lid & 3) * 2 + b;
            red[col * 33 + wr * 8 + (lid >> 2)] = qpart[nf * 2 + b];
        }
    }
    __syncthreads();
    if (tid < 128) {
        float q = 0.f;
#pragma unroll
        for (int i = 0; i < 32; i++) q += red[tid * 33 + i];
        int m = m0 + tid;
        out[(size_t)m * Cc + c] = -((1.0f - REGC) * q + REGC * g_dn2[(size_t)m * Cc + c]);
    }
}

// ---------------- orchestration ----------------
extern "C" void kernel_launch(void* const* d_in, const int* in_sizes, int n_in,
                              void* d_out, int out_size) {
    const float* X     = (const float*)d_in[0];
    const int*   y     = (const int*)d_in[1];
    const float* Xq    = (const float*)d_in[2];
    const float* m     = (const float*)d_in[3];
    const float* kappa = (const float*)d_in[4];
    const float* nu    = (const float*)d_in[5];
    const float* tdiag = (const float*)d_in[6];
    const float* tlow  = (const float*)d_in[7];
    float* out = (float*)d_out;

    cudaFuncSetAttribute((const void*)k_fused,
                         cudaFuncAttributeMaxDynamicSharedMemorySize, SM_FUSED_TOTAL);

    k_gather<<<1, Cc>>>(y);
    k_scalars<<<1, Cc>>>(kappa, nu);
    k_mu<<<dim3(Cc, Dd / 256), 256>>>(X, m, kappa);
    k_mun<<<Cc, 256>>>();
    k_buildL<<<(Dd * Dd) / 256, 256>>>(tdiag, tlow);
    k_base<<<dim3(16, 16), 256>>>(m, kappa);
    k_sigma<<<dim3(16, 16, Cc), 256>>>(X);

    for (int s = 0; s < 16; s++) {
        int rows = Dd - 64 * (s + 1);
        int yb = rows > 0 ? (rows + 127) / 128 : 1;
        k_chol_step<<<dim3(Cc, yb), 128>>>(s);
        if (rows > 0) {
            int nb = rows / 64;
            k_chol_syrk<<<dim3(nb, nb, Cc), 256>>>(s);
        }
    }

    // TRTRI: recursive doubling
    k_initI<<<(int)(((size_t)Cc * Dd * Dd) / 256), 256>>>();
    k_inv_diag<<<dim3(16, Cc), 64>>>();
    for (int s = 64; s <= 512; s *= 2) {
        int p = Dd / (2 * s);
        k_rec<<<dim3(s / 64, s / 64, p * Cc), 256>>>(s, 0);
        k_rec<<<dim3(s / 64, s / 64, p * Cc), 256>>>(s, 1);
    }

    k_splitU<<<(int)(((size_t)Cc * Dd * Dd) / 256), 256>>>();
    k_splitX<<<(int)(((size_t)Mq * Dd) / 256), 256>>>(Xq);
    k_v<<<dim3(Dd, Cc), 128>>>();
    k_dn<<<Mq, 128>>>(Xq);

    k_fused<<<dim3(Mq / 128, Cc), 256, SM_FUSED_TOTAL>>>(out);
}

// round 6
// speedup vs baseline: 1.6267x; 1.0333x over previous
#include <cuda_runtime.h>
#include <cuda_bf16.h>
#include <math.h>
#include <stdint.h>

#define Ncnt 4096
#define Dd   1024
#define Mq   4096
#define Cc   16
#define REGC 0.1f

// ---------------- scratch ----------------
__device__ int   g_cnt[Cc];
__device__ int   g_off[Cc];
__device__ int   g_idx[Ncnt];
__device__ float g_r[Cc];
__device__ float g_invden[Cc];
__device__ float g_mu[Cc*Dd];
__device__ float g_mun[Cc];
__device__ float g_L[Dd*Dd];
__device__ float g_B[Dd*Dd];
__device__ float g_Sig[(size_t)Cc*Dd*Dd];
__device__ float g_U[(size_t)Cc*Dd*Dd];           // zero-init .bss; only lower triangle ever written
__device__ float g_T[(size_t)Cc*512*512];
__device__ __nv_bfloat16 g_Uh[(size_t)Cc*Dd*Dd];  // zero-init; lower triangle written by producers
__device__ __nv_bfloat16 g_Ul[(size_t)Cc*Dd*Dd];
__device__ __nv_bfloat16 g_Xh[(size_t)Mq*Dd];
__device__ __nv_bfloat16 g_Xl[(size_t)Mq*Dd];
__device__ float g_v[Cc*Dd];
__device__ float g_dn2[(size_t)Mq*Cc];

// ---------------- helpers ----------------
__device__ __forceinline__ uint32_t smem_u32(const void* p) {
    uint32_t a;
    asm("{ .reg .u64 t; cvta.to.shared.u64 t, %1; cvt.u32.u64 %0, t; }" : "=r"(a) : "l"(p));
    return a;
}
__device__ __forceinline__ void cpa16(uint32_t dst, const void* src) {
    asm volatile("cp.async.cg.shared.global [%0], [%1], 16;" :: "r"(dst), "l"(src) : "memory");
}
__device__ __forceinline__ void cpa_commit() { asm volatile("cp.async.commit_group;" ::: "memory"); }
__device__ __forceinline__ void cpa_wait0()  { asm volatile("cp.async.wait_group 0;" ::: "memory"); }
__device__ __forceinline__ void cpa_wait1()  { asm volatile("cp.async.wait_group 1;" ::: "memory"); }
__device__ __forceinline__ void ldm_x4(uint32_t* r, uint32_t a) {
    asm volatile("ldmatrix.sync.aligned.m8n8.x4.shared.b16 {%0,%1,%2,%3}, [%4];"
        : "=r"(r[0]), "=r"(r[1]), "=r"(r[2]), "=r"(r[3]) : "r"(a));
}
__device__ __forceinline__ void mma_bf16(float* c, const uint32_t* a, uint32_t b0, uint32_t b1) {
    asm volatile("mma.sync.aligned.m16n8k16.row.col.f32.bf16.bf16.f32 "
        "{%0,%1,%2,%3}, {%4,%5,%6,%7}, {%8,%9}, {%0,%1,%2,%3};"
        : "+f"(c[0]), "+f"(c[1]), "+f"(c[2]), "+f"(c[3])
        : "r"(a[0]), "r"(a[1]), "r"(a[2]), "r"(a[3]), "r"(b0), "r"(b1));
}

// ---------------- fit-side small kernels ----------------
__global__ void k_gather(const int* __restrict__ y) {
    int c = threadIdx.x;
    if (c >= Cc) return;
    int cnt = 0;
    for (int i = 0; i < Ncnt; i++) cnt += (y[i] == c);
    g_cnt[c] = cnt;
    __syncthreads();
    int off = 0;
    for (int cc = 0; cc < c; cc++) off += g_cnt[cc];
    g_off[c] = off;
    int p = off;
    for (int i = 0; i < Ncnt; i++) if (y[i] == c) g_idx[p++] = i;
}

__global__ void k_scalars(const float* __restrict__ kappa, const float* __restrict__ nu) {
    int c = threadIdx.x;
    if (c >= Cc) return;
    float kap = fabsf(kappa[0]) + 1e-6f;
    float nu_ = fmaxf(nu[0], (float)Dd - 1.0f + 1e-6f);
    float Nj  = (float)g_cnt[c];
    g_r[c]      = kap + Nj;
    g_invden[c] = 1.0f / (nu_ + Nj + (float)Dd + 2.0f);
}

__global__ void k_mu(const float* __restrict__ X, const float* __restrict__ m,
                     const float* __restrict__ kappa) {
    int c = blockIdx.x;
    int j = blockIdx.y * 256 + threadIdx.x;
    int cnt = g_cnt[c], off = g_off[c];
    float s = 0.f;
    for (int k = 0; k < cnt; k++) s += X[(size_t)g_idx[off + k] * Dd + j];
    float kap = fabsf(kappa[0]) + 1e-6f;
    g_mu[c * Dd + j] = (kap * m[j] + s) / (kap + (float)cnt);
}

__global__ void k_mun() {
    int c = blockIdx.x, t = threadIdx.x;
    __shared__ float red[256];
    float a = 0.f;
    for (int d = t; d < Dd; d += 256) { float v = g_mu[c * Dd + d]; a += v * v; }
    red[t] = a; __syncthreads();
    for (int st = 128; st; st >>= 1) { if (t < st) red[t] += red[t + st]; __syncthreads(); }
    if (t == 0) g_mun[c] = red[0];
}

__global__ void k_buildL(const float* __restrict__ tdiag, const float* __restrict__ tlow) {
    int t = blockIdx.x * 256 + threadIdx.x;
    int i = t / Dd, j = t % Dd;
    float v;
    if (i == j)      v = fabsf(tdiag[i]);
    else if (i > j)  v = tlow[t];
    else             v = 0.f;
    g_L[t] = v;
}

// ---------------- SIMT GEMM tile helpers ----------------
__device__ __forceinline__ void mm_loadNT(float* sm, const float* __restrict__ G,
                                          int row0, int k0, int ld, int tid) {
    int i = tid >> 2;
    int q = (tid & 3) * 4;
    float4 v = *reinterpret_cast<const float4*>(G + (size_t)(row0 + i) * ld + k0 + q);
    sm[(q + 0) * 64 + i] = v.x;
    sm[(q + 1) * 64 + i] = v.y;
    sm[(q + 2) * 64 + i] = v.z;
    sm[(q + 3) * 64 + i] = v.w;
}
__device__ __forceinline__ void mm_loadT(float* sm, const float* __restrict__ G,
                                         int k0, int col0, int ld, int tid) {
    int kk = tid >> 4;
    int j  = (tid & 15) * 4;
    float4 v = *reinterpret_cast<const float4*>(G + (size_t)(k0 + kk) * ld + col0 + j);
    *reinterpret_cast<float4*>(sm + kk * 64 + j) = v;
}

#define MM_INNER(As, Bs, acc, ty, tx)                                     \
    _Pragma("unroll")                                                     \
    for (int kk = 0; kk < 16; kk++) {                                     \
        float4 a = *reinterpret_cast<float4*>((As) + kk * 64 + (ty) * 4); \
        float4 b = *reinterpret_cast<float4*>((Bs) + kk * 64 + (tx) * 4); \
        acc[0][0] += a.x * b.x; acc[0][1] += a.x * b.y;                   \
        acc[0][2] += a.x * b.z; acc[0][3] += a.x * b.w;                   \
        acc[1][0] += a.y * b.x; acc[1][1] += a.y * b.y;                   \
        acc[1][2] += a.y * b.z; acc[1][3] += a.y * b.w;                   \
        acc[2][0] += a.z * b.x; acc[2][1] += a.z * b.y;                   \
        acc[2][2] += a.z * b.z; acc[2][3] += a.z * b.w;                   \
        acc[3][0] += a.w * b.x; acc[3][1] += a.w * b.y;                   \
        acc[3][2] += a.w * b.z; acc[3][3] += a.w * b.w;                   \
    }

__global__ void k_base(const float* __restrict__ m, const float* __restrict__ kappa) {
    int bi = blockIdx.x, bj = blockIdx.y;
    if (bj > bi) return;
    int tid = threadIdx.x, tx = tid & 15, ty = tid >> 4;
    __shared__ float As[16 * 64], Bs[16 * 64];
    float acc[4][4] = {};
    int kchunks = (bj + 1) * 4;
    for (int kt = 0; kt < kchunks; kt++) {
        mm_loadNT(As, g_L, bi * 64, kt * 16, Dd, tid);
        mm_loadNT(Bs, g_L, bj * 64, kt * 16, Dd, tid);
        __syncthreads();
        MM_INNER(As, Bs, acc, ty, tx);
        __syncthreads();
    }
    float kap = fabsf(kappa[0]) + 1e-6f;
    for (int r = 0; r < 4; r++) {
        int i = bi * 64 + ty * 4 + r;
        for (int q = 0; q < 4; q++) {
            int j = bj * 64 + tx * 4 + q;
            g_B[(size_t)i * Dd + j] = acc[r][q] + kap * m[i] * m[j];
        }
    }
}

__global__ void k_sigma(const float* __restrict__ X) {
    int bi = blockIdx.x, bj = blockIdx.y, c = blockIdx.z;
    if (bj > bi) return;
    int tid = threadIdx.x, tx = tid & 15, ty = tid >> 4;
    int cnt = g_cnt[c], off = g_off[c];
    __shared__ float As[16 * 64], Bs[16 * 64];
    float acc[4][4] = {};
    int kk = tid >> 4;
    int jj = (tid & 15) * 4;
    for (int kt = 0; kt < cnt; kt += 16) {
        int krow = kt + kk;
        float4 va = make_float4(0.f, 0.f, 0.f, 0.f), vb = va;
        if (krow < cnt) {
            const float* row = X + (size_t)g_idx[off + krow] * Dd;
            va = *reinterpret_cast<const float4*>(row + bi * 64 + jj);
            vb = *reinterpret_cast<const float4*>(row + bj * 64 + jj);
        }
        *reinterpret_cast<float4*>(As + kk * 64 + jj) = va;
        *reinterpret_cast<float4*>(Bs + kk * 64 + jj) = vb;
        __syncthreads();
        MM_INNER(As, Bs, acc, ty, tx);
        __syncthreads();
    }
    float rc = g_r[c], inv = g_invden[c];
    float* Sg = g_Sig + (size_t)c * Dd * Dd;
    for (int r = 0; r < 4; r++) {
        int i = bi * 64 + ty * 4 + r;
        float mui = g_mu[c * Dd + i];
        for (int q = 0; q < 4; q++) {
            int j = bj * 64 + tx * 4 + q;
            float v = g_B[(size_t)i * Dd + j] + acc[r][q] - rc * mui * g_mu[c * Dd + j];
            Sg[(size_t)i * Dd + j] = v * inv;
        }
    }
}

// ---------------- Cholesky: merged diag+panel step, then SYRK ----------------
__global__ void k_chol_step(int s) {
    int c = blockIdx.x, t = threadIdx.x;   // 128 threads
    float* A = g_Sig + (size_t)c * Dd * Dd;
    __shared__ float Ld[64][65];
    __shared__ float zsh[64][128];
    for (int idx = t; idx < 64 * 64; idx += 128) {
        int r = idx >> 6, k = idx & 63;
        Ld[r][k] = A[(size_t)(s * 64 + r) * Dd + s * 64 + k];
    }
    __syncthreads();
    for (int j = 0; j < 64; j++) {
        if (t == 0) Ld[j][j] = sqrtf(Ld[j][j]);
        __syncthreads();
        float dinv = 1.0f / Ld[j][j];
        if (t > j && t < 64) Ld[t][j] *= dinv;
        __syncthreads();
        int k = j + 1 + t;
        if (k < 64) {
            float lkj = Ld[k][j];
            for (int r = k; r < 64; r++) Ld[r][k] -= Ld[r][j] * lkj;
        }
        __syncthreads();
    }
    if (blockIdx.y == 0) {
        for (int idx = t; idx < 64 * 64; idx += 128) {
            int r = idx >> 6, k = idx & 63;
            if (k <= r) A[(size_t)(s * 64 + r) * Dd + s * 64 + k] = Ld[r][k];
        }
    }
    int g = 64 * (s + 1) + blockIdx.y * 128 + t;
    if (g < Dd) {
        float* row = A + (size_t)g * Dd + s * 64;
        for (int j = 0; j < 64; j++) {
            float a0 = 0.f, a1 = 0.f;
            int k = 0;
            for (; k + 1 < j; k += 2) {
                a0 += Ld[j][k] * zsh[k][t];
                a1 += Ld[j][k + 1] * zsh[k + 1][t];
            }
            if (k < j) a0 += Ld[j][k] * zsh[k][t];
            float v = (row[j] - a0 - a1) / Ld[j][j];
            zsh[j][t] = v;
            row[j] = v;
        }
    }
}

__global__ void k_chol_syrk(int s) {
    int r0 = 64 * (s + 1);
    int bi = blockIdx.x, bj = blockIdx.y, c = blockIdx.z;
    if (bj > bi) return;
    int tid = threadIdx.x, tx = tid & 15, ty = tid >> 4;
    float* A = g_Sig + (size_t)c * Dd * Dd;
    int i0 = r0 + bi * 64, j0 = r0 + bj * 64;
    __shared__ float As[16 * 64], Bs[16 * 64];
    float acc[4][4] = {};
    for (int kt = 0; kt < 4; kt++) {
        mm_loadNT(As, A, i0, s * 64 + kt * 16, Dd, tid);
        mm_loadNT(Bs, A, j0, s * 64 + kt * 16, Dd, tid);
        __syncthreads();
        MM_INNER(As, Bs, acc, ty, tx);
        __syncthreads();
    }
    for (int r = 0; r < 4; r++) {
        int i = i0 + ty * 4 + r;
        for (int q = 0; q < 4; q++) {
            int j = j0 + tx * 4 + q;
            A[(size_t)i * Dd + j] -= acc[r][q];
        }
    }
}

// ---------------- TRTRI by recursive doubling ----------------
// invert all 64x64 diag blocks; emits fp32 U + bf16 splits
__global__ void k_inv_diag() {
    int b = blockIdx.x, c = blockIdx.y, t = threadIdx.x;
    const float* A = g_Sig + (size_t)c * Dd * Dd;
    float* Up = g_U + (size_t)c * Dd * Dd;
    __shared__ float Ld[64][65];
    __shared__ float V[64][65];
    for (int idx = t; idx < 64 * 64; idx += 64) {
        int r = idx >> 6, k = idx & 63;
        Ld[r][k] = A[(size_t)(b * 64 + r) * Dd + b * 64 + k];
    }
    __syncthreads();
    for (int r = 0; r < t; r++) V[r][t] = 0.f;
    for (int r = t; r < 64; r++) {
        float a0 = 0.f, a1 = 0.f;
        int k = t;
        for (; k + 1 < r; k += 2) {
            a0 += Ld[r][k] * V[k][t];
            a1 += Ld[r][k + 1] * V[k + 1][t];
        }
        if (k < r) a0 += Ld[r][k] * V[k][t];
        float base = (r == t) ? 1.f : 0.f;
        V[r][t] = (base - a0 - a1) / Ld[r][r];
    }
    __syncthreads();
    size_t ub = (size_t)c << 20;
    for (int idx = t; idx < 64 * 64; idx += 64) {
        int r = idx >> 6, k = idx & 63;
        float x = V[r][k];
        size_t o = (size_t)(b * 64 + r) * Dd + b * 64 + k;
        Up[o] = x;
        __nv_bfloat16 h = __float2bfloat16(x);
        g_Uh[ub + o] = h;
        g_Ul[ub + o] = __float2bfloat16(x - __bfloat162float(h));
    }
}

// level-combine GEMMs. mode 0: T = L21 * U_A ; mode 1: U21 = -U_C * T (+ splits)
__global__ void k_rec(int s, int mode) {
    int p = Dd / (2 * s);
    int bi = blockIdx.x, bj = blockIdx.y;
    int pair = blockIdx.z % p, c = blockIdx.z / p;
    int tid = threadIdx.x, tx = tid & 15, ty = tid >> 4;
    int rA = pair * 2 * s, rC = rA + s;
    const float* Sg = g_Sig + (size_t)c * Dd * Dd;
    float* Up = g_U + (size_t)c * Dd * Dd;
    float* T = g_T + (size_t)c * 512 * 512 + (size_t)pair * s * s;
    __shared__ float As[16 * 64], Bs[16 * 64];
    float acc[4][4] = {};
    if (mode == 0) {
        for (int kt = bj * 4; kt < s / 16; kt++) {
            mm_loadNT(As, Sg + (size_t)(rC + bi * 64) * Dd + rA, 0, kt * 16, Dd, tid);
            mm_loadT(Bs, Up + (size_t)rA * Dd + rA + bj * 64, kt * 16, 0, Dd, tid);
            __syncthreads();
            MM_INNER(As, Bs, acc, ty, tx);
            __syncthreads();
        }
        for (int r = 0; r < 4; r++)
            for (int q = 0; q < 4; q++)
                T[(size_t)(bi * 64 + ty * 4 + r) * s + bj * 64 + tx * 4 + q] = acc[r][q];
    } else {
        for (int kt = 0; kt < (bi + 1) * 4; kt++) {
            mm_loadNT(As, Up + (size_t)(rC + bi * 64) * Dd + rC, 0, kt * 16, Dd, tid);
            mm_loadT(Bs, T + bj * 64, kt * 16, 0, s, tid);
            __syncthreads();
            MM_INNER(As, Bs, acc, ty, tx);
            __syncthreads();
        }
        size_t ub = (size_t)c << 20;
        for (int r = 0; r < 4; r++)
            for (int q = 0; q < 4; q++) {
                float x = -acc[r][q];
                size_t o = (size_t)(rC + bi * 64 + ty * 4 + r) * Dd + rA + bj * 64 + tx * 4 + q;
                Up[o] = x;
                __nv_bfloat16 h = __float2bfloat16(x);
                g_Uh[ub + o] = h;
                g_Ul[ub + o] = __float2bfloat16(x - __bfloat162float(h));
            }
    }
}

// ---------------- Xq splits ----------------
__global__ void k_splitX(const float* __restrict__ Xq) {
    size_t t = (size_t)blockIdx.x * 256 + threadIdx.x;
    float x = Xq[t];
    __nv_bfloat16 h = __float2bfloat16(x);
    g_Xh[t] = h;
    g_Xl[t] = __float2bfloat16(x - __bfloat162float(h));
}

// v_c = U_c mu_c  (triangular extent)
__global__ void k_v() {
    int d = blockIdx.x, c = blockIdx.y, t = threadIdx.x;
    __shared__ float red[128];
    const float* Ur = g_U + ((size_t)c * Dd + d) * Dd;
    const float* mu = g_mu + c * Dd;
    float a = 0.f;
    for (int e = t; e <= d; e += 128) a += Ur[e] * mu[e];
    red[t] = a; __syncthreads();
    for (int st = 64; st; st >>= 1) { if (t < st) red[t] += red[t + st]; __syncthreads(); }
    if (t == 0) g_v[c * Dd + d] = red[0];
}

__global__ void k_dn(const float* __restrict__ Xq) {
    int m = blockIdx.x, t = threadIdx.x;
    __shared__ float red[17][129];
    float dc[16];
#pragma unroll
    for (int c = 0; c < 16; c++) dc[c] = 0.f;
    float s2 = 0.f;
    for (int i = 0; i < 8; i++) {
        int d = t + i * 128;
        float x = Xq[(size_t)m * Dd + d];
        s2 += x * x;
#pragma unroll
        for (int c = 0; c < 16; c++) dc[c] += x * g_mu[c * Dd + d];
    }
#pragma unroll
    for (int c = 0; c < 16; c++) red[c][t] = dc[c];
    red[16][t] = s2;
    __syncthreads();
    for (int st = 64; st; st >>= 1) {
        if (t < st) {
#pragma unroll
            for (int r = 0; r < 17; r++) red[r][t] += red[r][t + st];
        }
        __syncthreads();
    }
    if (t < 16)
        g_dn2[(size_t)m * Cc + t] = red[16][0] - 2.f * red[t][0] + g_mun[t];
}

// ---------------- fused mma.sync kernel (flat 72-chunk pipeline) ----------------
#define STAGE_BYTES 65536
#define TILE_BYTES  16384
#define SM_FUSED_TOTAL (2*STAGE_BYTES)

__device__ __forceinline__ void fused_prefetch(uint32_t sb, const __nv_bfloat16* Ah,
                                               const __nv_bfloat16* Al, int dt, int k0,
                                               int m0, int tid) {
    for (int idx = tid; idx < 1024; idx += 256) {
        int row = idx >> 3, ch = idx & 7;
        uint32_t dsw = row * 128 + ((ch ^ (row & 7)) << 4);
        size_t gu = (size_t)(dt * 128 + row) * Dd + k0 + ch * 8;
        size_t gx = (size_t)(m0 + row) * Dd + k0 + ch * 8;
        cpa16(sb + dsw, Ah + gu);
        cpa16(sb + TILE_BYTES + dsw, Al + gu);
        cpa16(sb + 2 * TILE_BYTES + dsw, g_Xh + gx);
        cpa16(sb + 3 * TILE_BYTES + dsw, g_Xl + gx);
    }
}

extern "C" __global__ void __launch_bounds__(256, 1)
k_fused(float* __restrict__ out) {
    extern __shared__ char sm[];
    uint32_t smb = smem_u32(sm);
    int tid = threadIdx.x;
    int wid = tid >> 5, lid = tid & 31;
    int wr = wid >> 1, wc = wid & 1;
    int sub = lid >> 3, r8 = lid & 7;
    int m0 = blockIdx.x * 128;
    int c = blockIdx.y;

    const __nv_bfloat16* Ah = g_Uh + ((size_t)c << 20);
    const __nv_bfloat16* Al = g_Ul + ((size_t)c << 20);

    float acc[2][8][4];
#pragma unroll
    for (int a = 0; a < 2; a++)
#pragma unroll
        for (int b = 0; b < 8; b++)
#pragma unroll
            for (int d = 0; d < 4; d++) acc[a][b][d] = 0.f;
    float qpart[16];
#pragma unroll
    for (int i = 0; i < 16; i++) qpart[i] = 0.f;

    int arow_base0 = wr * 32 + (sub & 1) * 8 + r8;
    int acko = sub >> 1;
    int brow_base = (sub >> 1) * 8 + r8;
    int bcko = sub & 1;

    // 72 chunks: (dt, kb) with kb < 2*(dt+1)
    int dt = 0, kb = 0;
    fused_prefetch(smb, Ah, Al, 0, 0, m0, tid);
    cpa_commit();

    for (int ci = 0; ci < 72; ci++) {
        int st = ci & 1;
        int ndt = dt, nkb = kb + 1;
        if (nkb == 2 * (dt + 1)) { ndt = dt + 1; nkb = 0; }
        if (ci + 1 < 72) {
            fused_prefetch(smb + (st ^ 1) * STAGE_BYTES, Ah, Al, ndt, nkb * 64, m0, tid);
            cpa_commit();
            cpa_wait1();
        } else {
            cpa_wait0();
        }
        __syncthreads();

        uint32_t uhb = smb + st * STAGE_BYTES;
        uint32_t ulb = uhb + TILE_BYTES;
        uint32_t xhb = uhb + 2 * TILE_BYTES;
        uint32_t xlb = uhb + 3 * TILE_BYTES;
#pragma unroll
        for (int ks = 0; ks < 4; ks++) {
            int k2 = ks * 2;
            uint32_t ah[2][4], al2[2][4], bh[4][4], bl[4][4];
#pragma unroll
            for (int mf = 0; mf < 2; mf++) {
                int row = arow_base0 + mf * 16;
                uint32_t off = row * 128 + (((k2 + acko) ^ (row & 7)) << 4);
                ldm_x4(ah[mf], uhb + off);
                ldm_x4(al2[mf], ulb + off);
            }
#pragma unroll
            for (int nf2 = 0; nf2 < 4; nf2++) {
                int row = brow_base + (wc * 64 + nf2 * 16);
                uint32_t off = row * 128 + (((k2 + bcko) ^ (row & 7)) << 4);
                ldm_x4(bh[nf2], xhb + off);
                ldm_x4(bl[nf2], xlb + off);
            }
#pragma unroll
            for (int mf = 0; mf < 2; mf++) {
#pragma unroll
                for (int nf = 0; nf < 8; nf++) {
                    uint32_t b0h = bh[nf >> 1][(nf & 1) * 2];
                    uint32_t b1h = bh[nf >> 1][(nf & 1) * 2 + 1];
                    uint32_t b0l = bl[nf >> 1][(nf & 1) * 2];
                    uint32_t b1l = bl[nf >> 1][(nf & 1) * 2 + 1];
                    mma_bf16(acc[mf][nf], ah[mf], b0h, b1h);
                    mma_bf16(acc[mf][nf], ah[mf], b0l, b1l);
                    mma_bf16(acc[mf][nf], al2[mf], b0h, b1h);
                }
            }
        }
        // epilogue on last chunk of this d-tile (register-only; overlaps in-flight prefetch)
        if (kb == 2 * (dt + 1) - 1) {
#pragma unroll
            for (int mf = 0; mf < 2; mf++) {
                int dg = dt * 128 + wr * 32 + mf * 16 + (lid >> 2);
                float v0 = g_v[c * Dd + dg];
                float v1 = g_v[c * Dd + dg + 8];
#pragma unroll
                for (int nf = 0; nf < 8; nf++) {
                    float z;
                    z = acc[mf][nf][0] - v0; qpart[nf * 2 + 0] += z * z;
                    z = acc[mf][nf][1] - v0; qpart[nf * 2 + 1] += z * z;
                    z = acc[mf][nf][2] - v1; qpart[nf * 2 + 0] += z * z;
                    z = acc[mf][nf][3] - v1; qpart[nf * 2 + 1] += z * z;
                    acc[mf][nf][0] = 0.f; acc[mf][nf][1] = 0.f;
                    acc[mf][nf][2] = 0.f; acc[mf][nf][3] = 0.f;
                }
            }
        }
        __syncthreads();
        dt = ndt; kb = nkb;
    }

    float* red = reinterpret_cast<float*>(sm);
#pragma unroll
    for (int nf = 0; nf < 8; nf++) {
#pragma unroll
        for (int b = 0; b < 2; b++) {
            int col = wc * 64 + nf * 8 + (lid & 3) * 2 + b;
            red[col * 33 + wr * 8 + (lid >> 2)] = qpart[nf * 2 + b];
        }
    }
    __syncthreads();
    if (tid < 128) {
        float q = 0.f;
#pragma unroll
        for (int i = 0; i < 32; i++) q += red[tid * 33 + i];
        int m = m0 + tid;
        out[(size_t)m * Cc + c] = -((1.0f - REGC) * q + REGC * g_dn2[(size_t)m * Cc + c]);
    }
}

// ---------------- orchestration ----------------
extern "C" void kernel_launch(void* const* d_in, const int* in_sizes, int n_in,
                              void* d_out, int out_size) {
    const float* X     = (const float*)d_in[0];
    const int*   y     = (const int*)d_in[1];
    const float* Xq    = (const float*)d_in[2];
    const float* m     = (const float*)d_in[3];
    const float* kappa = (const float*)d_in[4];
    const float* nu    = (const float*)d_in[5];
    const float* tdiag = (const float*)d_in[6];
    const float* tlow  = (const float*)d_in[7];
    float* out = (float*)d_out;

    cudaFuncSetAttribute((const void*)k_fused,
                         cudaFuncAttributeMaxDynamicSharedMemorySize, SM_FUSED_TOTAL);

    k_gather<<<1, Cc>>>(y);
    k_scalars<<<1, Cc>>>(kappa, nu);
    k_mu<<<dim3(Cc, Dd / 256), 256>>>(X, m, kappa);
    k_mun<<<Cc, 256>>>();
    k_buildL<<<(Dd * Dd) / 256, 256>>>(tdiag, tlow);
    k_base<<<dim3(16, 16), 256>>>(m, kappa);
    k_sigma<<<dim3(16, 16, Cc), 256>>>(X);

    for (int s = 0; s < 16; s++) {
        int rows = Dd - 64 * (s + 1);
        int yb = rows > 0 ? (rows + 127) / 128 : 1;
        k_chol_step<<<dim3(Cc, yb), 128>>>(s);
        if (rows > 0) {
            int nb = rows / 64;
            k_chol_syrk<<<dim3(nb, nb, Cc), 256>>>(s);
        }
    }

    // TRTRI: recursive doubling (splits emitted by producers; upper triangle stays .bss zero)
    k_inv_diag<<<dim3(16, Cc), 64>>>();
    for (int s = 64; s <= 512; s *= 2) {
        int p = Dd / (2 * s);
        k_rec<<<dim3(s / 64, s / 64, p * Cc), 256>>>(s, 0);
        k_rec<<<dim3(s / 64, s / 64, p * Cc), 256>>>(s, 1);
    }

    k_splitX<<<(int)(((size_t)Mq * Dd) / 256), 256>>>(Xq);
    k_v<<<dim3(Dd, Cc), 128>>>();
    k_dn<<<Mq, 128>>>(Xq);

    k_fused<<<dim3(Mq / 128, Cc), 256, SM_FUSED_TOTAL>>>(out);
}